// round 13
// baseline (speedup 1.0000x reference)
#include <cuda_runtime.h>

#define BB 8
#define NV 207
#define TT 12
#define LL 2
#define NGH 8
#define ALPHA 0.2f
#define NN (NV*NV)
#define ST 20   // k-major stride for activation buffers (floats)
#define PT 14   // stride for partial-sum buffers
#define XR 418  // GAT slab row stride (per t)

typedef unsigned long long u64t;

// scratch: gat output (B*N groups, layout per group: e*12+t)
__device__ float g_out[BB*NV*TT*64];

__device__ __forceinline__ float warp_sum(float v){
  #pragma unroll
  for (int o=16;o;o>>=1) v += __shfl_xor_sync(0xffffffffu, v, o);
  return v;
}
__device__ __forceinline__ u64t pack2(float v){
  u64t r; asm("mov.b64 %0, {%1, %1};" : "=l"(r) : "f"(v)); return r;
}
__device__ __forceinline__ void fma2(u64t &acc, u64t a, u64t b){
  asm("fma.rn.f32x2 %0, %1, %2, %0;" : "+l"(acc) : "l"(a), "l"(b));
}

// ---------------------------------------------------------------------------
// K1: GAT + conv1 (exact R12 winner).
// ---------------------------------------------------------------------------
__global__ void __launch_bounds__(128) k_gat(
    const float* __restrict__ x,      // (B,C,N,T)
    const int*   __restrict__ adj,    // (B,N,N)
    const float* __restrict__ W2,     // (8,4,2)
    const float* __restrict__ ga,     // (8,2)
    const float* __restrict__ gb,     // (8,2)
    const float* __restrict__ w1,     // (4,64)
    const float* __restrict__ b1)     // (64)
{
  __shared__ float xsa[TT*XR];     // [t][2n+c]
  __shared__ int   adjs[2*NV];
  __shared__ float w1s[256];
  __shared__ float b1s[64];

  int b  = blockIdx.x;
  int i0 = blockIdx.y * 2;
  int tid = threadIdx.x;

  const float* xb = x + (long)b*2*NV*TT;
  for (int idx=tid; idx<2*NV*TT; idx+=128){
    int c = idx/(NV*TT); int r = idx - c*NV*TT;
    int n = r/TT, t = r - n*TT;
    xsa[t*XR + 2*n + c] = xb[idx];
  }
  int nrows = (NV - i0) < 2 ? (NV - i0) : 2;
  for (int idx=tid; idx<nrows*NV; idx+=128){
    int ii = idx / NV, j = idx - ii*NV;
    adjs[ii*NV+j] = adj[((long)b*NV + i0+ii)*NV + j];
  }
  for (int idx=tid; idx<256; idx+=128) w1s[idx]=w1[idx];
  if (tid<64) b1s[tid]=b1[tid];
  __syncthreads();

  int warp = tid>>5, lane = tid&31;

  for (int task = warp; task < 24; task += 4){
    int t  = task % 12;
    int ii = task / 12;
    int i  = i0 + ii;
    if (i >= NV) continue;
    const int* arow = adjs + ii*NV;
    const float* xrow = xsa + t*XR;

    int pk[7];
    #pragma unroll
    for (int jj=0; jj<7; jj++){
      int j = jj*32 + lane;
      bool valid = j < NV;
      int jc = valid ? j : 0;
      bool ok = valid && (arow[jc] > 0);
      int r0 = 2*(i*NV + jc);
      int a0 = (r0   < NN) ? (2*i + (jc>=104)) : ((jc>=104) ? 2*jc-207 : 2*jc);
      int a1 = (r0+1 < NN) ? (2*i + (jc>=103)) : ((jc>=103) ? 2*jc-206 : 2*jc+1);
      pk[jj] = a0 | (a1<<9) | ((ok?1:0)<<18) | (jc<<19);
    }

    float acc0=0.f, acc1=0.f;
    #pragma unroll
    for (int hg=0; hg<2; hg++){
      float w2r[4][4][2], ar[4][2];
      #pragma unroll
      for (int hh=0;hh<4;hh++){
        int h = hg*4+hh;
        #pragma unroll
        for (int k=0;k<4;k++){
          w2r[hh][k][0]=__ldg(W2+(h*4+k)*2+0);
          w2r[hh][k][1]=__ldg(W2+(h*4+k)*2+1);
        }
        ar[hh][0]=__ldg(ga+h*2); ar[hh][1]=__ldg(ga+h*2+1);
      }
      float d[4]={0,0,0,0}, n0[4]={0,0,0,0}, n1[4]={0,0,0,0};
      #pragma unroll
      for (int jj=0; jj<7; jj++){
        int p = pk[jj];
        int a0 =  p        & 511;
        int a1 = (p >> 9)  & 511;
        float okf = (float)((p >> 18) & 1);
        int jc = (p >> 19);
        float2 ca = *(const float2*)(xrow + 2*a0);
        float2 cb = *(const float2*)(xrow + 2*a1);
        float2 xj = *(const float2*)(xrow + 2*jc);
        #pragma unroll
        for (int hh=0;hh<4;hh++){
          float we0 = ca.x*w2r[hh][0][0] + ca.y*w2r[hh][1][0] + cb.x*w2r[hh][2][0] + cb.y*w2r[hh][3][0];
          float we1 = ca.x*w2r[hh][0][1] + ca.y*w2r[hh][1][1] + cb.x*w2r[hh][2][1] + cb.y*w2r[hh][3][1];
          we0 = (we0 > 0.f) ? we0 : ALPHA*we0;
          we1 = (we1 > 0.f) ? we1 : ALPHA*we1;
          float e = we0*ar[hh][0] + we1*ar[hh][1];
          float w = okf * __expf(e);
          d[hh]  += w;
          n0[hh] += w*xj.x;
          n1[hh] += w*xj.y;
        }
      }
      #pragma unroll
      for (int off=16; off; off>>=1){
        #pragma unroll
        for (int hh=0;hh<4;hh++){
          d[hh]  += __shfl_xor_sync(0xffffffffu, d[hh],  off);
          n0[hh] += __shfl_xor_sync(0xffffffffu, n0[hh], off);
          n1[hh] += __shfl_xor_sync(0xffffffffu, n1[hh], off);
        }
      }
      #pragma unroll
      for (int hh=0;hh<4;hh++){
        int h = hg*4+hh;
        float inv = 1.0f/d[hh];
        float z0 = n0[hh]*inv + __ldg(gb+h*2+0);
        float z1 = n1[hh]*inv + __ldg(gb+h*2+1);
        acc0 += 1.f - __fdividef(2.f, __expf(2.f*z0)+1.f);
        acc1 += 1.f - __fdividef(2.f, __expf(2.f*z1)+1.f);
      }
    }
    acc0 *= 0.125f; acc1 *= 0.125f;

    float xi0 = xrow[2*i], xi1 = xrow[2*i+1];
    long obase = (long)(b*NV + i)*768;
    #pragma unroll
    for (int r=0;r<2;r++){
      int e = lane + r*32;
      g_out[obase + e*12 + t] = xi0*w1s[e] + xi1*w1s[64+e]
                              + acc0*w1s[128+e] + acc1*w1s[192+e] + b1s[e];
    }
  }
}

// ---------------------------------------------------------------------------
// gemm4h: 4 columns x 6 tokens per thread. Half-warps split the 12 tokens:
// half 0 -> tokens 0-5 (bytes 0-23 of row), half 1 -> tokens 6-11 (24-47).
// Per warp per k: LDS.128 + LDS.64 (acts) + 2x LDG.64 (weights, halves dedup)
// = 4 wavefronts for 12 warp FFMA2 issues.
// Accumulators: aP0/aP1 = tokens from the 16B load, aS = tokens from the 8B.
// ---------------------------------------------------------------------------
__device__ __forceinline__ void gemm4h(const float* __restrict__ sIn,
    const float* __restrict__ W, int ldw,
    int q, int coff, int half, int k0, int nk,
    u64t aP0[4], u64t aP1[4], u64t aS[4]){
  const int off128 = half ? 32 : 0;
  const int off64  = half ? 24 : 16;
  #pragma unroll 4
  for (int k=k0; k<k0+nk; k++){
    const float* wr = W + (long)k*ldw;
    float2 wa = __ldg((const float2*)wr + q);
    float2 wb = __ldg((const float2*)(wr + coff) + q);
    u64t b0=pack2(wa.x), b1=pack2(wa.y), b2=pack2(wb.x), b3=pack2(wb.y);
    const char* base = (const char*)(sIn + k*ST);
    ulonglong2 p = *(const ulonglong2*)(base + off128);
    u64t s = *(const u64t*)(base + off64);
    fma2(aP0[0], p.x, b0); fma2(aP0[1], p.x, b1); fma2(aP0[2], p.x, b2); fma2(aP0[3], p.x, b3);
    fma2(aP1[0], p.y, b0); fma2(aP1[1], p.y, b1); fma2(aP1[2], p.y, b2); fma2(aP1[3], p.y, b3);
    fma2(aS[0],  s,   b0); fma2(aS[1],  s,   b1); fma2(aS[2],  s,   b2); fma2(aS[3],  s,   b3);
  }
}

// Store one column's 6 tokens into standard row layout [col][0..11].
// half 0: tokens (0-1)=P0 (2-3)=P1 (4-5)=S at d[0..5]
// half 1: tokens (6-7)=S (8-9)=P0 (10-11)=P1 at d[6..11]
__device__ __forceinline__ void store_h(float* d, int half, u64t p0, u64t p1, u64t s){
  float2* f = (float2*)(d + 6*half);
  if (half==0){ f[0]=*(const float2*)&p0; f[1]=*(const float2*)&p1; f[2]=*(const float2*)&s; }
  else        { f[0]=*(const float2*)&s;  f[1]=*(const float2*)&p0; f[2]=*(const float2*)&p1; }
}
__device__ __forceinline__ void store_h_relu(float* d, int half, u64t p0, u64t p1, u64t s, float b){
  float2 v0=*(const float2*)&p0, v1=*(const float2*)&p1, v2=*(const float2*)&s;
  v0.x=fmaxf(v0.x+b,0.f); v0.y=fmaxf(v0.y+b,0.f);
  v1.x=fmaxf(v1.x+b,0.f); v1.y=fmaxf(v1.y+b,0.f);
  v2.x=fmaxf(v2.x+b,0.f); v2.y=fmaxf(v2.y+b,0.f);
  float2* f = (float2*)(d + 6*half);
  if (half==0){ f[0]=v0; f[1]=v1; f[2]=v2; }
  else        { f[0]=v2; f[1]=v0; f[2]=v1; }
}

#define Z4(A) {A[0]=0;A[1]=0;A[2]=0;A[3]=0;}

// ---------------------------------------------------------------------------
// K2: BOTH transformer layers + conv2/conv3 head fused.
// grid 1656 (=B*N), block 256. smem arena 46KB.
// ---------------------------------------------------------------------------
#define S_QQ 0
#define S_Q  1280
#define S_K  2560
#define S_V  3840
#define S_X1 5120
#define S_H  6400      // 5120 floats
#define SM_TOT 11520

__global__ void __launch_bounds__(256, 4) k_fused(
    const float* __restrict__ temb,
    const float* __restrict__ Wq, const float* __restrict__ Wk,
    const float* __restrict__ Wv, const float* __restrict__ Wo,
    const float* __restrict__ bo,
    const float* __restrict__ ln1g, const float* __restrict__ ln1b,
    const float* __restrict__ ln2g, const float* __restrict__ ln2b,
    const float* __restrict__ fw1, const float* __restrict__ fb1,
    const float* __restrict__ fw2, const float* __restrict__ fb2,
    const float* __restrict__ lng, const float* __restrict__ lnb,
    const float* __restrict__ w2c, const float* __restrict__ b2c,
    const float* __restrict__ w3c, const float* __restrict__ b3c,
    float* __restrict__ outp)
{
  __shared__ __align__(16) float sm[SM_TOT];

  int tid = threadIdx.x;
  int warp = tid>>5, lane = tid&31;
  int qh = lane & 15, half = lane >> 4;
  long base = (long)blockIdx.x * 768;

  for (int idx=tid; idx<768; idx+=256){
    int e = idx/12, t = idx - e*12;
    sm[S_QQ + e*ST+t] = g_out[base+idx] + __ldg(temb + t*64+e);
  }
  __syncthreads();

  for (int l=0; l<LL; l++){
    const float* Wq_  = Wq  + l*4096;
    const float* Wk_  = Wk  + l*4096;
    const float* Wv_  = Wv  + l*4096;
    const float* Wo_  = Wo  + l*4096;
    const float* bo_  = bo  + l*64;
    const float* ln1g_= ln1g+ l*64;  const float* ln1b_= ln1b+ l*64;
    const float* ln2g_= ln2g+ l*64;  const float* ln2b_= ln2b+ l*64;
    const float* fw1_ = fw1 + l*16384; const float* fb1_ = fb1 + l*256;
    const float* fw2_ = fw2 + l*16384; const float* fb2_ = fb2 + l*64;
    const float* lng_ = lng + l*64;  const float* lnb_ = lnb + l*64;

    // ---- Q,K,V: 6 warps = 3 mats x 2 kgroups; each warp covers all 64 cols ----
    if (tid < 192){
      int m  = warp >> 1;
      int kg = warp & 1;
      const float* W = (m==0 ? Wq_ : (m==1 ? Wk_ : Wv_));
      int bi = m*2 + kg;
      float* pb = (bi < 5) ? (sm + S_H + bi*896) : (sm + S_X1);
      u64t aP0[4], aP1[4], aS[4]; Z4(aP0) Z4(aP1) Z4(aS)
      gemm4h(sm + S_QQ, W, 64, qh, 32, half, kg*32, 32, aP0, aP1, aS);
      store_h(pb + (2*qh   )*PT, half, aP0[0], aP1[0], aS[0]);
      store_h(pb + (2*qh+1 )*PT, half, aP0[1], aP1[1], aS[1]);
      store_h(pb + (2*qh+32)*PT, half, aP0[2], aP1[2], aS[2]);
      store_h(pb + (2*qh+33)*PT, half, aP0[3], aP1[3], aS[3]);
    }
    __syncthreads();
    // sum partials -> Q,K,V
    for (int idx=tid; idx<2304; idx+=256){
      int m = idx/768, r = idx - m*768;
      int e = r/12, t = r - e*12;
      const float* p0 = (m*2   < 5) ? (sm + S_H + (m*2  )*896) : (sm + S_X1);
      const float* p1 = (m*2+1 < 5) ? (sm + S_H + (m*2+1)*896) : (sm + S_X1);
      float v = p0[e*PT+t] + p1[e*PT+t];
      float* dst = sm + (m==0 ? S_Q : (m==1 ? S_K : S_V));
      dst[e*ST+t] = v;
    }
    __syncthreads();

    // ---- attention scores: 192 threads, 3 scores each ----
    if (tid < 192){
      int h = tid / 48;
      int rem = tid - h*48;
      int t2 = rem >> 2;
      int sq = (rem & 3) * 3;
      const float* qp = sm + S_Q + (h*16)*ST + t2;
      float q[16];
      #pragma unroll
      for (int d=0; d<16; d++) q[d] = qp[d*ST];
      #pragma unroll
      for (int j=0;j<3;j++){
        int s = sq + j;
        const float* kp = sm + S_K + (h*16)*ST + s;
        float sum=0.f;
        #pragma unroll
        for (int d=0;d<16;d++) sum += q[d]*kp[d*ST];
        sm[S_H + (h*12+t2)*12 + s] = sum*0.25f;
      }
    }
    __syncthreads();
    if (tid < 48){
      float* row = sm + S_H + tid*12;
      float mxv = row[0];
      #pragma unroll
      for (int s=1;s<12;s++) mxv = fmaxf(mxv,row[s]);
      float evv[12]; float sum=0.f;
      #pragma unroll
      for (int s=0;s<12;s++){ evv[s]=__expf(row[s]-mxv); sum+=evv[s]; }
      float inv = 1.f/sum;
      #pragma unroll
      for (int s=0;s<12;s++) row[s]=evv[s]*inv;
    }
    __syncthreads();

    // ---- ctx = att @ V (float4 loads; into S_Q) ----
    for (int idx=tid; idx<768; idx+=256){
      int e = idx/12, t2 = idx - e*12, h = e>>4;
      const float4* a4 = (const float4*)(sm + S_H + (h*12+t2)*12);
      const float4* v4 = (const float4*)(sm + S_V + e*ST);
      float4 a0=a4[0], a1=a4[1], a2=a4[2];
      float4 v0=v4[0], v1=v4[1], v2=v4[2];
      float sum = a0.x*v0.x + a0.y*v0.y + a0.z*v0.z + a0.w*v0.w
                + a1.x*v1.x + a1.y*v1.y + a1.z*v1.z + a1.w*v1.w
                + a2.x*v2.x + a2.y*v2.y + a2.z*v2.z + a2.w*v2.w;
      sm[S_Q + e*ST+t2] = sum;
    }
    __syncthreads();

    // ---- attn_out = ctx @ Wo : 4 warps = 4 kgroups; partials -> S_H ----
    if (tid < 128){
      int kg = warp;
      u64t aP0[4], aP1[4], aS[4]; Z4(aP0) Z4(aP1) Z4(aS)
      gemm4h(sm + S_Q, Wo_, 64, qh, 32, half, kg*16, 16, aP0, aP1, aS);
      float* pb = sm + S_H + kg*896;
      store_h(pb + (2*qh   )*PT, half, aP0[0], aP1[0], aS[0]);
      store_h(pb + (2*qh+1 )*PT, half, aP0[1], aP1[1], aS[1]);
      store_h(pb + (2*qh+32)*PT, half, aP0[2], aP1[2], aS[2]);
      store_h(pb + (2*qh+33)*PT, half, aP0[3], aP1[3], aS[3]);
    }
    __syncthreads();

    // ---- LN1 merged with Wo-sum + bias + residual; -> S_X1 ----
    for (int t = warp; t < 12; t += 8){
      int e0 = lane, e1 = lane+32;
      float v0 = sm[S_H+e0*PT+t]+sm[S_H+896+e0*PT+t]+sm[S_H+1792+e0*PT+t]+sm[S_H+2688+e0*PT+t]
               + bo_[e0] + sm[S_QQ+e0*ST+t];
      float v1 = sm[S_H+e1*PT+t]+sm[S_H+896+e1*PT+t]+sm[S_H+1792+e1*PT+t]+sm[S_H+2688+e1*PT+t]
               + bo_[e1] + sm[S_QQ+e1*ST+t];
      float s  = warp_sum(v0+v1);
      float s2 = warp_sum(v0*v0+v1*v1);
      float mean = s*(1.f/64.f);
      float var  = s2*(1.f/64.f) - mean*mean;
      float r = rsqrtf(var + 1e-5f);
      sm[S_X1+e0*ST+t] = (v0-mean)*r*ln1g_[e0] + ln1b_[e0];
      sm[S_X1+e1*ST+t] = (v1-mean)*r*ln1g_[e1] + ln1b_[e1];
    }
    __syncthreads();

    // ---- FF1: 4 warps, each 64 cols, full k=64; relu -> S_H ----
    if (tid < 128){
      int wbase = warp*64;
      u64t aP0[4], aP1[4], aS[4]; Z4(aP0) Z4(aP1) Z4(aS)
      gemm4h(sm + S_X1, fw1_ + wbase, 256, qh, 32, half, 0, 64, aP0, aP1, aS);
      int c0 = wbase + 2*qh, c1 = c0+1, c2 = c0+32, c3 = c0+33;
      store_h_relu(sm + S_H + c0*ST, half, aP0[0], aP1[0], aS[0], fb1_[c0]);
      store_h_relu(sm + S_H + c1*ST, half, aP0[1], aP1[1], aS[1], fb1_[c1]);
      store_h_relu(sm + S_H + c2*ST, half, aP0[2], aP1[2], aS[2], fb1_[c2]);
      store_h_relu(sm + S_H + c3*ST, half, aP0[3], aP1[3], aS[3], fb1_[c3]);
    }
    __syncthreads();

    // ---- FF2: 4 warps = 4 kgroups of 64; partials -> S_Q region ----
    if (tid < 128){
      int kg = warp;
      u64t aP0[4], aP1[4], aS[4]; Z4(aP0) Z4(aP1) Z4(aS)
      gemm4h(sm + S_H, fw2_, 64, qh, 32, half, kg*64, 64, aP0, aP1, aS);
      float* pb = sm + S_Q + kg*896;
      store_h(pb + (2*qh   )*PT, half, aP0[0], aP1[0], aS[0]);
      store_h(pb + (2*qh+1 )*PT, half, aP0[1], aP1[1], aS[1]);
      store_h(pb + (2*qh+32)*PT, half, aP0[2], aP1[2], aS[2]);
      store_h(pb + (2*qh+33)*PT, half, aP0[3], aP1[3], aS[3]);
    }
    __syncthreads();

    // ---- LN2 merged with FF2-sum + bias + residual(X1); -> S_X1 ----
    for (int t = warp; t < 12; t += 8){
      int e0 = lane, e1 = lane+32;
      float v0 = sm[S_Q+e0*PT+t]+sm[S_Q+896+e0*PT+t]+sm[S_Q+1792+e0*PT+t]+sm[S_Q+2688+e0*PT+t]
               + fb2_[e0] + sm[S_X1+e0*ST+t];
      float v1 = sm[S_Q+e1*PT+t]+sm[S_Q+896+e1*PT+t]+sm[S_Q+1792+e1*PT+t]+sm[S_Q+2688+e1*PT+t]
               + fb2_[e1] + sm[S_X1+e1*ST+t];
      float s  = warp_sum(v0+v1);
      float s2 = warp_sum(v0*v0+v1*v1);
      float mean = s*(1.f/64.f);
      float var  = s2*(1.f/64.f) - mean*mean;
      float r = rsqrtf(var + 1e-5f);
      sm[S_X1+e0*ST+t] = (v0-mean)*r*ln2g_[e0] + ln2b_[e0];
      sm[S_X1+e1*ST+t] = (v1-mean)*r*ln2g_[e1] + ln2b_[e1];
    }
    __syncthreads();

    // ---- LN3 merged with residual (QQ - temb) ----
    for (int t = warp; t < 12; t += 8){
      int e0 = lane, e1 = lane+32;
      float te0 = __ldg(temb + t*64+e0), te1 = __ldg(temb + t*64+e1);
      float v0 = sm[S_X1+e0*ST+t] + sm[S_QQ+e0*ST+t] - te0;
      float v1 = sm[S_X1+e1*ST+t] + sm[S_QQ+e1*ST+t] - te1;
      float s  = warp_sum(v0+v1);
      float s2 = warp_sum(v0*v0+v1*v1);
      float mean = s*(1.f/64.f);
      float var  = s2*(1.f/64.f) - mean*mean;
      float r = rsqrtf(var + 1e-5f);
      float o0 = (v0-mean)*r*lng_[e0] + lnb_[e0];
      float o1 = (v1-mean)*r*lng_[e1] + lnb_[e1];
      if (l+1 < LL){
        sm[S_QQ+e0*ST+t] = o0 + te0;
        sm[S_QQ+e1*ST+t] = o1 + te1;
      } else {
        sm[S_K+e0*ST+t] = o0;
        sm[S_K+e1*ST+t] = o1;
      }
    }
    __syncthreads();
  }

  // ---- head: conv2 over t (relu) + conv3 over e. out in S_K ----
  if (tid < 192){
    int o = tid>>4, es = (tid&15)*4;
    float w2row[12];
    #pragma unroll
    for (int t=0;t<12;t++) w2row[t] = __ldg(w2c + o*12 + t);
    float b2v = __ldg(b2c + o);
    float acc = 0.f;
    #pragma unroll
    for (int q=0;q<4;q++){
      int e = es + q;
      const float* rowp = sm + S_K + e*ST;
      float v = b2v;
      #pragma unroll
      for (int t=0;t<12;t++) v += rowp[t]*w2row[t];
      v = fmaxf(v, 0.f);
      acc += v * __ldg(w3c + e);
    }
    #pragma unroll
    for (int off=8; off; off>>=1) acc += __shfl_xor_sync(0xffffffffu, acc, off);
    if ((tid&15)==0) outp[(long)blockIdx.x*12 + o] = acc + __ldg(b3c);
  }
}

// ---------------------------------------------------------------------------
extern "C" void kernel_launch(void* const* d_in, const int* in_sizes, int n_in,
                              void* d_out, int out_size) {
  const float* x       = (const float*)d_in[0];
  const int*   adj     = (const int*)  d_in[1];
  const float* gat_W2  = (const float*)d_in[2];
  const float* gat_a   = (const float*)d_in[3];
  const float* gat_b   = (const float*)d_in[4];
  const float* conv1_w = (const float*)d_in[5];
  const float* conv1_b = (const float*)d_in[6];
  const float* temb    = (const float*)d_in[7];
  const float* Wq      = (const float*)d_in[8];
  const float* Wk      = (const float*)d_in[9];
  const float* Wv      = (const float*)d_in[10];
  const float* Wo      = (const float*)d_in[11];
  const float* bo      = (const float*)d_in[12];
  const float* ln1_g   = (const float*)d_in[13];
  const float* ln1_b   = (const float*)d_in[14];
  const float* ln2_g   = (const float*)d_in[15];
  const float* ln2_b   = (const float*)d_in[16];
  const float* ff_w1   = (const float*)d_in[17];
  const float* ff_b1   = (const float*)d_in[18];
  const float* ff_w2   = (const float*)d_in[19];
  const float* ff_b2   = (const float*)d_in[20];
  const float* lng     = (const float*)d_in[21];
  const float* lnb     = (const float*)d_in[22];
  const float* conv2_w = (const float*)d_in[23];
  const float* conv2_b = (const float*)d_in[24];
  const float* conv3_w = (const float*)d_in[25];
  const float* conv3_b = (const float*)d_in[26];
  float* outp = (float*)d_out;

  dim3 g1(BB, (NV + 1) / 2);
  k_gat<<<g1, 128>>>(x, adj, gat_W2, gat_a, gat_b, conv1_w, conv1_b);

  k_fused<<<BB*NV, 256>>>(temb, Wq, Wk, Wv, Wo, bo,
                          ln1_g, ln1_b, ln2_g, ln2_b,
                          ff_w1, ff_b1, ff_w2, ff_b2,
                          lng, lnb,
                          conv2_w, conv2_b, conv3_w, conv3_b, outp);
}

// round 14
// speedup vs baseline: 1.0077x; 1.0077x over previous
#include <cuda_runtime.h>

#define BB 8
#define NV 207
#define TT 12
#define LL 2
#define NGH 8
#define ALPHA 0.2f
#define NN (NV*NV)
#define ST 20   // k-major stride for main activation buffers (floats)
#define HT 12   // stride for FF1 activation buffer (48B rows, 16B aligned)
#define PT 14   // stride for partial-sum buffers
#define XR 418  // GAT slab row stride (per t)

typedef unsigned long long u64t;

// scratch: gat output (B*N groups, layout per group: e*12+t)
__device__ float g_out[BB*NV*TT*64];

__device__ __forceinline__ float warp_sum(float v){
  #pragma unroll
  for (int o=16;o;o>>=1) v += __shfl_xor_sync(0xffffffffu, v, o);
  return v;
}
__device__ __forceinline__ u64t pack2(float v){
  u64t r; asm("mov.b64 %0, {%1, %1};" : "=l"(r) : "f"(v)); return r;
}
__device__ __forceinline__ void fma2(u64t &acc, u64t a, u64t b){
  asm("fma.rn.f32x2 %0, %1, %2, %0;" : "+l"(acc) : "l"(a), "l"(b));
}

// ---------------------------------------------------------------------------
// K1: GAT + conv1 (exact R12 winner).
// ---------------------------------------------------------------------------
__global__ void __launch_bounds__(128) k_gat(
    const float* __restrict__ x,      // (B,C,N,T)
    const int*   __restrict__ adj,    // (B,N,N)
    const float* __restrict__ W2,     // (8,4,2)
    const float* __restrict__ ga,     // (8,2)
    const float* __restrict__ gb,     // (8,2)
    const float* __restrict__ w1,     // (4,64)
    const float* __restrict__ b1)     // (64)
{
  __shared__ float xsa[TT*XR];     // [t][2n+c]
  __shared__ int   adjs[2*NV];
  __shared__ float w1s[256];
  __shared__ float b1s[64];

  int b  = blockIdx.x;
  int i0 = blockIdx.y * 2;
  int tid = threadIdx.x;

  const float* xb = x + (long)b*2*NV*TT;
  for (int idx=tid; idx<2*NV*TT; idx+=128){
    int c = idx/(NV*TT); int r = idx - c*NV*TT;
    int n = r/TT, t = r - n*TT;
    xsa[t*XR + 2*n + c] = xb[idx];
  }
  int nrows = (NV - i0) < 2 ? (NV - i0) : 2;
  for (int idx=tid; idx<nrows*NV; idx+=128){
    int ii = idx / NV, j = idx - ii*NV;
    adjs[ii*NV+j] = adj[((long)b*NV + i0+ii)*NV + j];
  }
  for (int idx=tid; idx<256; idx+=128) w1s[idx]=w1[idx];
  if (tid<64) b1s[tid]=b1[tid];
  __syncthreads();

  int warp = tid>>5, lane = tid&31;

  for (int task = warp; task < 24; task += 4){
    int t  = task % 12;
    int ii = task / 12;
    int i  = i0 + ii;
    if (i >= NV) continue;
    const int* arow = adjs + ii*NV;
    const float* xrow = xsa + t*XR;

    int pk[7];
    #pragma unroll
    for (int jj=0; jj<7; jj++){
      int j = jj*32 + lane;
      bool valid = j < NV;
      int jc = valid ? j : 0;
      bool ok = valid && (arow[jc] > 0);
      int r0 = 2*(i*NV + jc);
      int a0 = (r0   < NN) ? (2*i + (jc>=104)) : ((jc>=104) ? 2*jc-207 : 2*jc);
      int a1 = (r0+1 < NN) ? (2*i + (jc>=103)) : ((jc>=103) ? 2*jc-206 : 2*jc+1);
      pk[jj] = a0 | (a1<<9) | ((ok?1:0)<<18) | (jc<<19);
    }

    float acc0=0.f, acc1=0.f;
    #pragma unroll
    for (int hg=0; hg<2; hg++){
      float w2r[4][4][2], ar[4][2];
      #pragma unroll
      for (int hh=0;hh<4;hh++){
        int h = hg*4+hh;
        #pragma unroll
        for (int k=0;k<4;k++){
          w2r[hh][k][0]=__ldg(W2+(h*4+k)*2+0);
          w2r[hh][k][1]=__ldg(W2+(h*4+k)*2+1);
        }
        ar[hh][0]=__ldg(ga+h*2); ar[hh][1]=__ldg(ga+h*2+1);
      }
      float d[4]={0,0,0,0}, n0[4]={0,0,0,0}, n1[4]={0,0,0,0};
      #pragma unroll
      for (int jj=0; jj<7; jj++){
        int p = pk[jj];
        int a0 =  p        & 511;
        int a1 = (p >> 9)  & 511;
        float okf = (float)((p >> 18) & 1);
        int jc = (p >> 19);
        float2 ca = *(const float2*)(xrow + 2*a0);
        float2 cb = *(const float2*)(xrow + 2*a1);
        float2 xj = *(const float2*)(xrow + 2*jc);
        #pragma unroll
        for (int hh=0;hh<4;hh++){
          float we0 = ca.x*w2r[hh][0][0] + ca.y*w2r[hh][1][0] + cb.x*w2r[hh][2][0] + cb.y*w2r[hh][3][0];
          float we1 = ca.x*w2r[hh][0][1] + ca.y*w2r[hh][1][1] + cb.x*w2r[hh][2][1] + cb.y*w2r[hh][3][1];
          we0 = (we0 > 0.f) ? we0 : ALPHA*we0;
          we1 = (we1 > 0.f) ? we1 : ALPHA*we1;
          float e = we0*ar[hh][0] + we1*ar[hh][1];
          float w = okf * __expf(e);
          d[hh]  += w;
          n0[hh] += w*xj.x;
          n1[hh] += w*xj.y;
        }
      }
      #pragma unroll
      for (int off=16; off; off>>=1){
        #pragma unroll
        for (int hh=0;hh<4;hh++){
          d[hh]  += __shfl_xor_sync(0xffffffffu, d[hh],  off);
          n0[hh] += __shfl_xor_sync(0xffffffffu, n0[hh], off);
          n1[hh] += __shfl_xor_sync(0xffffffffu, n1[hh], off);
        }
      }
      #pragma unroll
      for (int hh=0;hh<4;hh++){
        int h = hg*4+hh;
        float inv = 1.0f/d[hh];
        float z0 = n0[hh]*inv + __ldg(gb+h*2+0);
        float z1 = n1[hh]*inv + __ldg(gb+h*2+1);
        acc0 += 1.f - __fdividef(2.f, __expf(2.f*z0)+1.f);
        acc1 += 1.f - __fdividef(2.f, __expf(2.f*z1)+1.f);
      }
    }
    acc0 *= 0.125f; acc1 *= 0.125f;

    float xi0 = xrow[2*i], xi1 = xrow[2*i+1];
    long obase = (long)(b*NV + i)*768;
    #pragma unroll
    for (int r=0;r<2;r++){
      int e = lane + r*32;
      g_out[obase + e*12 + t] = xi0*w1s[e] + xi1*w1s[64+e]
                              + acc0*w1s[128+e] + acc1*w1s[192+e] + b1s[e];
    }
  }
}

// ---------------------------------------------------------------------------
// gemm2: 2 cols x 12 tokens (R8/R12 winner shape), parametric act stride.
// ---------------------------------------------------------------------------
__device__ __forceinline__ void gemm2(const float* __restrict__ sIn, int lds,
                                      const float* __restrict__ W, int ldw,
                                      int c0, int c1, int k0, int nk,
                                      u64t A[6], u64t Bc[6]){
  #pragma unroll 4
  for (int k=k0; k<k0+nk; k++){
    const float* wr = W + (long)k*ldw;
    u64t wa = pack2(__ldg(wr+c0));
    u64t wb = pack2(__ldg(wr+c1));
    const ulonglong2* a = (const ulonglong2*)(sIn + k*lds);
    ulonglong2 v0 = a[0], v1 = a[1], v2 = a[2];
    fma2(A[0], v0.x, wa); fma2(Bc[0], v0.x, wb);
    fma2(A[1], v0.y, wa); fma2(Bc[1], v0.y, wb);
    fma2(A[2], v1.x, wa); fma2(Bc[2], v1.x, wb);
    fma2(A[3], v1.y, wa); fma2(Bc[3], v1.y, wb);
    fma2(A[4], v2.x, wa); fma2(Bc[4], v2.x, wb);
    fma2(A[5], v2.y, wa); fma2(Bc[5], v2.y, wb);
  }
}

// gemm2h: 2 cols x 6 tokens (one token-half), full accumulation, direct store.
__device__ __forceinline__ void gemm2h(const float* __restrict__ sIn,
                                       const float* __restrict__ W, int ldw,
                                       int c0, int c1, int half, int k0, int nk,
                                       u64t A[3], u64t Bc[3]){
  const int off16 = half ? 32 : 0;
  const int off8  = half ? 24 : 16;
  #pragma unroll 4
  for (int k=k0; k<k0+nk; k++){
    const float* wr = W + (long)k*ldw;
    u64t wa = pack2(__ldg(wr+c0));
    u64t wb = pack2(__ldg(wr+c1));
    const char* base = (const char*)(sIn + k*ST);
    ulonglong2 p = *(const ulonglong2*)(base + off16);
    u64t s = *(const u64t*)(base + off8);
    fma2(A[0], p.x, wa); fma2(Bc[0], p.x, wb);
    fma2(A[1], p.y, wa); fma2(Bc[1], p.y, wb);
    fma2(A[2], s,   wa); fma2(Bc[2], s,   wb);
  }
}
// store a token-half: half0 tokens (0,1)(2,3)(4,5)=A0,A1,A2 ; half1 (6,7)=A2 (8,9)=A0 (10,11)=A1
__device__ __forceinline__ void store_half(float* d, int half, const u64t A[3]){
  float2* f = (float2*)(d + 6*half);
  if (half==0){ f[0]=*(const float2*)&A[0]; f[1]=*(const float2*)&A[1]; f[2]=*(const float2*)&A[2]; }
  else        { f[0]=*(const float2*)&A[2]; f[1]=*(const float2*)&A[0]; f[2]=*(const float2*)&A[1]; }
}

__device__ __forceinline__ void store6(float* dst, const u64t A[6]){
  #pragma unroll
  for (int p=0;p<6;p++) ((float2*)dst)[p] = *(const float2*)&A[p];
}

// ---------------------------------------------------------------------------
// K2: BOTH transformer layers + conv2/conv3 head fused.
// grid 1656, block 256, smem 39.9KB -> 5 blocks/SM (regs capped 51).
// ---------------------------------------------------------------------------
#define S_QQ 0
#define S_Q  1280
#define S_K  2560
#define S_V  3840
#define S_X1 5120
#define S_H  6400      // 3584 floats: FF1 acts [256][HT=12] (3072) / partials 4x896
#define SM_TOT 9984

__global__ void __launch_bounds__(256, 5) k_fused(
    const float* __restrict__ temb,
    const float* __restrict__ Wq, const float* __restrict__ Wk,
    const float* __restrict__ Wv, const float* __restrict__ Wo,
    const float* __restrict__ bo,
    const float* __restrict__ ln1g, const float* __restrict__ ln1b,
    const float* __restrict__ ln2g, const float* __restrict__ ln2b,
    const float* __restrict__ fw1, const float* __restrict__ fb1,
    const float* __restrict__ fw2, const float* __restrict__ fb2,
    const float* __restrict__ lng, const float* __restrict__ lnb,
    const float* __restrict__ w2c, const float* __restrict__ b2c,
    const float* __restrict__ w3c, const float* __restrict__ b3c,
    float* __restrict__ outp)
{
  __shared__ __align__(16) float sm[SM_TOT];

  int tid = threadIdx.x;
  int warp = tid>>5, lane = tid&31;
  long base = (long)blockIdx.x * 768;

  for (int idx=tid; idx<768; idx+=256){
    int e = idx/12, t = idx - e*12;
    sm[S_QQ + e*ST+t] = g_out[base+idx] + __ldg(temb + t*64+e);
  }
  __syncthreads();

  for (int l=0; l<LL; l++){
    const float* Wq_  = Wq  + l*4096;
    const float* Wk_  = Wk  + l*4096;
    const float* Wv_  = Wv  + l*4096;
    const float* Wo_  = Wo  + l*4096;
    const float* bo_  = bo  + l*64;
    const float* ln1g_= ln1g+ l*64;  const float* ln1b_= ln1b+ l*64;
    const float* ln2g_= ln2g+ l*64;  const float* ln2b_= ln2b+ l*64;
    const float* fw1_ = fw1 + l*16384; const float* fb1_ = fb1 + l*256;
    const float* fw2_ = fw2 + l*16384; const float* fb2_ = fb2 + l*64;
    const float* lng_ = lng + l*64;  const float* lnb_ = lnb + l*64;

    // ---- Q,K,V token-split: 192 threads = 3 mats x 32 cols x 2 halves.
    //      Full k=64 per thread, direct store (no partials, no sum pass). ----
    if (tid < 192){
      int m    = tid >> 6;
      int half = (tid >> 5) & 1;
      int e2   = tid & 31;
      const float* W = (m==0 ? Wq_ : (m==1 ? Wk_ : Wv_));
      float* dst = sm + (m==0 ? S_Q : (m==1 ? S_K : S_V));
      u64t A[3]={0,0,0}, B[3]={0,0,0};
      gemm2h(sm + S_QQ, W, 64, e2, e2+32, half, 0, 64, A, B);
      store_half(dst + e2*ST, half, A);
      store_half(dst + (e2+32)*ST, half, B);
    }
    __syncthreads();

    // ---- attention scores: 192 threads, 3 scores each ----
    if (tid < 192){
      int h = tid / 48;
      int rem = tid - h*48;
      int t2 = rem >> 2;
      int sq = (rem & 3) * 3;
      const float* qp = sm + S_Q + (h*16)*ST + t2;
      float q[16];
      #pragma unroll
      for (int d=0; d<16; d++) q[d] = qp[d*ST];
      #pragma unroll
      for (int j=0;j<3;j++){
        int s = sq + j;
        const float* kp = sm + S_K + (h*16)*ST + s;
        float sum=0.f;
        #pragma unroll
        for (int d=0;d<16;d++) sum += q[d]*kp[d*ST];
        sm[S_H + (h*12+t2)*12 + s] = sum*0.25f;
      }
    }
    __syncthreads();
    if (tid < 48){
      float* row = sm + S_H + tid*12;
      float mxv = row[0];
      #pragma unroll
      for (int s=1;s<12;s++) mxv = fmaxf(mxv,row[s]);
      float evv[12]; float sum=0.f;
      #pragma unroll
      for (int s=0;s<12;s++){ evv[s]=__expf(row[s]-mxv); sum+=evv[s]; }
      float inv = 1.f/sum;
      #pragma unroll
      for (int s=0;s<12;s++) row[s]=evv[s]*inv;
    }
    __syncthreads();

    // ---- ctx = att @ V (float4 loads; into S_Q) ----
    for (int idx=tid; idx<768; idx+=256){
      int e = idx/12, t2 = idx - e*12, h = e>>4;
      const float4* a4 = (const float4*)(sm + S_H + (h*12+t2)*12);
      const float4* v4 = (const float4*)(sm + S_V + e*ST);
      float4 a0=a4[0], a1=a4[1], a2=a4[2];
      float4 v0=v4[0], v1=v4[1], v2=v4[2];
      float sum = a0.x*v0.x + a0.y*v0.y + a0.z*v0.z + a0.w*v0.w
                + a1.x*v1.x + a1.y*v1.y + a1.z*v1.z + a1.w*v1.w
                + a2.x*v2.x + a2.y*v2.y + a2.z*v2.z + a2.w*v2.w;
      sm[S_Q + e*ST+t2] = sum;
    }
    __syncthreads();

    // ---- attn_out = ctx @ Wo : 128 threads, 4 kgroups; partials -> S_H ----
    if (tid < 128){
      int kg = tid>>5, e2 = tid&31;
      u64t A[6]={0,0,0,0,0,0}, B[6]={0,0,0,0,0,0};
      gemm2(sm + S_Q, ST, Wo_, 64, e2, e2+32, kg*16, 16, A, B);
      float* pb = sm + S_H + kg*896;
      store6(pb + e2*PT, A);
      store6(pb + (e2+32)*PT, B);
    }
    __syncthreads();

    // ---- LN1 merged with Wo-sum + bias + residual; -> S_X1 ----
    for (int t = warp; t < 12; t += 8){
      int e0 = lane, e1 = lane+32;
      float v0 = sm[S_H+e0*PT+t]+sm[S_H+896+e0*PT+t]+sm[S_H+1792+e0*PT+t]+sm[S_H+2688+e0*PT+t]
               + bo_[e0] + sm[S_QQ+e0*ST+t];
      float v1 = sm[S_H+e1*PT+t]+sm[S_H+896+e1*PT+t]+sm[S_H+1792+e1*PT+t]+sm[S_H+2688+e1*PT+t]
               + bo_[e1] + sm[S_QQ+e1*ST+t];
      float s  = warp_sum(v0+v1);
      float s2 = warp_sum(v0*v0+v1*v1);
      float mean = s*(1.f/64.f);
      float var  = s2*(1.f/64.f) - mean*mean;
      float r = rsqrtf(var + 1e-5f);
      sm[S_X1+e0*ST+t] = (v0-mean)*r*ln1g_[e0] + ln1b_[e0];
      sm[S_X1+e1*ST+t] = (v1-mean)*r*ln1g_[e1] + ln1b_[e1];
    }
    __syncthreads();

    // ---- FF1: 128 threads, cols (f, f+128), k=64; relu -> S_H stride HT ----
    if (tid < 128){
      int f = tid;
      u64t A[6]={0,0,0,0,0,0}, B[6]={0,0,0,0,0,0};
      gemm2(sm + S_X1, ST, fw1_, 256, f, f+128, 0, 64, A, B);
      float ba = fb1_[f], bb2 = fb1_[f+128];
      float* dA = sm + S_H + f*HT;
      float* dB = sm + S_H + (f+128)*HT;
      #pragma unroll
      for (int p=0;p<6;p++){
        float2 va = *(const float2*)&A[p];
        float2 vb = *(const float2*)&B[p];
        va.x = fmaxf(va.x+ba,0.f);  va.y = fmaxf(va.y+ba,0.f);
        vb.x = fmaxf(vb.x+bb2,0.f); vb.y = fmaxf(vb.y+bb2,0.f);
        ((float2*)dA)[p] = va;
        ((float2*)dB)[p] = vb;
      }
    }
    __syncthreads();

    // ---- FF2: 128 threads, 4 kgroups of 64 (acts stride HT); partials -> S_Q ----
    if (tid < 128){
      int kg = tid>>5, e2 = tid&31;
      u64t A[6]={0,0,0,0,0,0}, B[6]={0,0,0,0,0,0};
      gemm2(sm + S_H, HT, fw2_, 64, e2, e2+32, kg*64, 64, A, B);
      float* pb = sm + S_Q + kg*896;
      store6(pb + e2*PT, A);
      store6(pb + (e2+32)*PT, B);
    }
    __syncthreads();

    // ---- LN2 merged with FF2-sum + bias + residual(X1); -> S_X1 ----
    for (int t = warp; t < 12; t += 8){
      int e0 = lane, e1 = lane+32;
      float v0 = sm[S_Q+e0*PT+t]+sm[S_Q+896+e0*PT+t]+sm[S_Q+1792+e0*PT+t]+sm[S_Q+2688+e0*PT+t]
               + fb2_[e0] + sm[S_X1+e0*ST+t];
      float v1 = sm[S_Q+e1*PT+t]+sm[S_Q+896+e1*PT+t]+sm[S_Q+1792+e1*PT+t]+sm[S_Q+2688+e1*PT+t]
               + fb2_[e1] + sm[S_X1+e1*ST+t];
      float s  = warp_sum(v0+v1);
      float s2 = warp_sum(v0*v0+v1*v1);
      float mean = s*(1.f/64.f);
      float var  = s2*(1.f/64.f) - mean*mean;
      float r = rsqrtf(var + 1e-5f);
      sm[S_X1+e0*ST+t] = (v0-mean)*r*ln2g_[e0] + ln2b_[e0];
      sm[S_X1+e1*ST+t] = (v1-mean)*r*ln2g_[e1] + ln2b_[e1];
    }
    __syncthreads();

    // ---- LN3 merged with residual (QQ - temb) ----
    for (int t = warp; t < 12; t += 8){
      int e0 = lane, e1 = lane+32;
      float te0 = __ldg(temb + t*64+e0), te1 = __ldg(temb + t*64+e1);
      float v0 = sm[S_X1+e0*ST+t] + sm[S_QQ+e0*ST+t] - te0;
      float v1 = sm[S_X1+e1*ST+t] + sm[S_QQ+e1*ST+t] - te1;
      float s  = warp_sum(v0+v1);
      float s2 = warp_sum(v0*v0+v1*v1);
      float mean = s*(1.f/64.f);
      float var  = s2*(1.f/64.f) - mean*mean;
      float r = rsqrtf(var + 1e-5f);
      float o0 = (v0-mean)*r*lng_[e0] + lnb_[e0];
      float o1 = (v1-mean)*r*lng_[e1] + lnb_[e1];
      if (l+1 < LL){
        sm[S_QQ+e0*ST+t] = o0 + te0;
        sm[S_QQ+e1*ST+t] = o1 + te1;
      } else {
        sm[S_K+e0*ST+t] = o0;
        sm[S_K+e1*ST+t] = o1;
      }
    }
    __syncthreads();
  }

  // ---- head: conv2 over t (relu) + conv3 over e. out in S_K ----
  if (tid < 192){
    int o = tid>>4, es = (tid&15)*4;
    float w2row[12];
    #pragma unroll
    for (int t=0;t<12;t++) w2row[t] = __ldg(w2c + o*12 + t);
    float b2v = __ldg(b2c + o);
    float acc = 0.f;
    #pragma unroll
    for (int q=0;q<4;q++){
      int e = es + q;
      const float* rowp = sm + S_K + e*ST;
      float v = b2v;
      #pragma unroll
      for (int t=0;t<12;t++) v += rowp[t]*w2row[t];
      v = fmaxf(v, 0.f);
      acc += v * __ldg(w3c + e);
    }
    #pragma unroll
    for (int off=8; off; off>>=1) acc += __shfl_xor_sync(0xffffffffu, acc, off);
    if ((tid&15)==0) outp[(long)blockIdx.x*12 + o] = acc + __ldg(b3c);
  }
}

// ---------------------------------------------------------------------------
extern "C" void kernel_launch(void* const* d_in, const int* in_sizes, int n_in,
                              void* d_out, int out_size) {
  const float* x       = (const float*)d_in[0];
  const int*   adj     = (const int*)  d_in[1];
  const float* gat_W2  = (const float*)d_in[2];
  const float* gat_a   = (const float*)d_in[3];
  const float* gat_b   = (const float*)d_in[4];
  const float* conv1_w = (const float*)d_in[5];
  const float* conv1_b = (const float*)d_in[6];
  const float* temb    = (const float*)d_in[7];
  const float* Wq      = (const float*)d_in[8];
  const float* Wk      = (const float*)d_in[9];
  const float* Wv      = (const float*)d_in[10];
  const float* Wo      = (const float*)d_in[11];
  const float* bo      = (const float*)d_in[12];
  const float* ln1_g   = (const float*)d_in[13];
  const float* ln1_b   = (const float*)d_in[14];
  const float* ln2_g   = (const float*)d_in[15];
  const float* ln2_b   = (const float*)d_in[16];
  const float* ff_w1   = (const float*)d_in[17];
  const float* ff_b1   = (const float*)d_in[18];
  const float* ff_w2   = (const float*)d_in[19];
  const float* ff_b2   = (const float*)d_in[20];
  const float* lng     = (const float*)d_in[21];
  const float* lnb     = (const float*)d_in[22];
  const float* conv2_w = (const float*)d_in[23];
  const float* conv2_b = (const float*)d_in[24];
  const float* conv3_w = (const float*)d_in[25];
  const float* conv3_b = (const float*)d_in[26];
  float* outp = (float*)d_out;

  dim3 g1(BB, (NV + 1) / 2);
  k_gat<<<g1, 128>>>(x, adj, gat_W2, gat_a, gat_b, conv1_w, conv1_b);

  k_fused<<<BB*NV, 256>>>(temb, Wq, Wk, Wv, Wo, bo,
                          ln1_g, ln1_b, ln2_g, ln2_b,
                          ff_w1, ff_b1, ff_w2, ff_b2,
                          lng, lnb,
                          conv2_w, conv2_b, conv3_w, conv3_b, outp);
}

// round 15
// speedup vs baseline: 1.0525x; 1.0445x over previous
#include <cuda_runtime.h>

#define BB 8
#define NV 207
#define TT 12
#define LL 2
#define NGH 8
#define ALPHA 0.2f
#define NN (NV*NV)
#define ST 20   // k-major stride for activation buffers (floats)
#define PT 14   // stride for partial-sum buffers
#define XR 418  // GAT slab row stride (per t)

typedef unsigned long long u64t;

// scratch: gat output (B*N groups, layout per group: e*12+t)
__device__ float g_out[BB*NV*TT*64];

__device__ __forceinline__ float warp_sum(float v){
  #pragma unroll
  for (int o=16;o;o>>=1) v += __shfl_xor_sync(0xffffffffu, v, o);
  return v;
}
__device__ __forceinline__ u64t pack2(float v){
  u64t r; asm("mov.b64 %0, {%1, %1};" : "=l"(r) : "f"(v)); return r;
}
__device__ __forceinline__ void fma2(u64t &acc, u64t a, u64t b){
  asm("fma.rn.f32x2 %0, %1, %2, %0;" : "+l"(acc) : "l"(a), "l"(b));
}

// ---------------------------------------------------------------------------
// K1: GAT + conv1 (exact R12 winner).
// ---------------------------------------------------------------------------
__global__ void __launch_bounds__(128) k_gat(
    const float* __restrict__ x,      // (B,C,N,T)
    const int*   __restrict__ adj,    // (B,N,N)
    const float* __restrict__ W2,     // (8,4,2)
    const float* __restrict__ ga,     // (8,2)
    const float* __restrict__ gb,     // (8,2)
    const float* __restrict__ w1,     // (4,64)
    const float* __restrict__ b1)     // (64)
{
  __shared__ float xsa[TT*XR];     // [t][2n+c]
  __shared__ int   adjs[2*NV];
  __shared__ float w1s[256];
  __shared__ float b1s[64];

  int b  = blockIdx.x;
  int i0 = blockIdx.y * 2;
  int tid = threadIdx.x;

  const float* xb = x + (long)b*2*NV*TT;
  for (int idx=tid; idx<2*NV*TT; idx+=128){
    int c = idx/(NV*TT); int r = idx - c*NV*TT;
    int n = r/TT, t = r - n*TT;
    xsa[t*XR + 2*n + c] = xb[idx];
  }
  int nrows = (NV - i0) < 2 ? (NV - i0) : 2;
  for (int idx=tid; idx<nrows*NV; idx+=128){
    int ii = idx / NV, j = idx - ii*NV;
    adjs[ii*NV+j] = adj[((long)b*NV + i0+ii)*NV + j];
  }
  for (int idx=tid; idx<256; idx+=128) w1s[idx]=w1[idx];
  if (tid<64) b1s[tid]=b1[tid];
  __syncthreads();

  int warp = tid>>5, lane = tid&31;

  for (int task = warp; task < 24; task += 4){
    int t  = task % 12;
    int ii = task / 12;
    int i  = i0 + ii;
    if (i >= NV) continue;
    const int* arow = adjs + ii*NV;
    const float* xrow = xsa + t*XR;

    int pk[7];
    #pragma unroll
    for (int jj=0; jj<7; jj++){
      int j = jj*32 + lane;
      bool valid = j < NV;
      int jc = valid ? j : 0;
      bool ok = valid && (arow[jc] > 0);
      int r0 = 2*(i*NV + jc);
      int a0 = (r0   < NN) ? (2*i + (jc>=104)) : ((jc>=104) ? 2*jc-207 : 2*jc);
      int a1 = (r0+1 < NN) ? (2*i + (jc>=103)) : ((jc>=103) ? 2*jc-206 : 2*jc+1);
      pk[jj] = a0 | (a1<<9) | ((ok?1:0)<<18) | (jc<<19);
    }

    float acc0=0.f, acc1=0.f;
    #pragma unroll
    for (int hg=0; hg<2; hg++){
      float w2r[4][4][2], ar[4][2];
      #pragma unroll
      for (int hh=0;hh<4;hh++){
        int h = hg*4+hh;
        #pragma unroll
        for (int k=0;k<4;k++){
          w2r[hh][k][0]=__ldg(W2+(h*4+k)*2+0);
          w2r[hh][k][1]=__ldg(W2+(h*4+k)*2+1);
        }
        ar[hh][0]=__ldg(ga+h*2); ar[hh][1]=__ldg(ga+h*2+1);
      }
      float d[4]={0,0,0,0}, n0[4]={0,0,0,0}, n1[4]={0,0,0,0};
      #pragma unroll
      for (int jj=0; jj<7; jj++){
        int p = pk[jj];
        int a0 =  p        & 511;
        int a1 = (p >> 9)  & 511;
        float okf = (float)((p >> 18) & 1);
        int jc = (p >> 19);
        float2 ca = *(const float2*)(xrow + 2*a0);
        float2 cb = *(const float2*)(xrow + 2*a1);
        float2 xj = *(const float2*)(xrow + 2*jc);
        #pragma unroll
        for (int hh=0;hh<4;hh++){
          float we0 = ca.x*w2r[hh][0][0] + ca.y*w2r[hh][1][0] + cb.x*w2r[hh][2][0] + cb.y*w2r[hh][3][0];
          float we1 = ca.x*w2r[hh][0][1] + ca.y*w2r[hh][1][1] + cb.x*w2r[hh][2][1] + cb.y*w2r[hh][3][1];
          we0 = (we0 > 0.f) ? we0 : ALPHA*we0;
          we1 = (we1 > 0.f) ? we1 : ALPHA*we1;
          float e = we0*ar[hh][0] + we1*ar[hh][1];
          float w = okf * __expf(e);
          d[hh]  += w;
          n0[hh] += w*xj.x;
          n1[hh] += w*xj.y;
        }
      }
      #pragma unroll
      for (int off=16; off; off>>=1){
        #pragma unroll
        for (int hh=0;hh<4;hh++){
          d[hh]  += __shfl_xor_sync(0xffffffffu, d[hh],  off);
          n0[hh] += __shfl_xor_sync(0xffffffffu, n0[hh], off);
          n1[hh] += __shfl_xor_sync(0xffffffffu, n1[hh], off);
        }
      }
      #pragma unroll
      for (int hh=0;hh<4;hh++){
        int h = hg*4+hh;
        float inv = 1.0f/d[hh];
        float z0 = n0[hh]*inv + __ldg(gb+h*2+0);
        float z1 = n1[hh]*inv + __ldg(gb+h*2+1);
        acc0 += 1.f - __fdividef(2.f, __expf(2.f*z0)+1.f);
        acc1 += 1.f - __fdividef(2.f, __expf(2.f*z1)+1.f);
      }
    }
    acc0 *= 0.125f; acc1 *= 0.125f;

    float xi0 = xrow[2*i], xi1 = xrow[2*i+1];
    long obase = (long)(b*NV + i)*768;
    #pragma unroll
    for (int r=0;r<2;r++){
      int e = lane + r*32;
      g_out[obase + e*12 + t] = xi0*w1s[e] + xi1*w1s[64+e]
                              + acc0*w1s[128+e] + acc1*w1s[192+e] + b1s[e];
    }
  }
}

// ---------------------------------------------------------------------------
// gemm2: 2 cols x 12 tokens (R12 winner shape).
// ---------------------------------------------------------------------------
__device__ __forceinline__ void gemm2(const float* __restrict__ sIn,
                                      const float* __restrict__ W, int ldw,
                                      int c0, int c1, int k0, int nk,
                                      u64t A[6], u64t Bc[6]){
  #pragma unroll 4
  for (int k=k0; k<k0+nk; k++){
    const float* wr = W + (long)k*ldw;
    u64t wa = pack2(__ldg(wr+c0));
    u64t wb = pack2(__ldg(wr+c1));
    const ulonglong2* a = (const ulonglong2*)(sIn + k*ST);
    ulonglong2 v0 = a[0], v1 = a[1], v2 = a[2];
    fma2(A[0], v0.x, wa); fma2(Bc[0], v0.x, wb);
    fma2(A[1], v0.y, wa); fma2(Bc[1], v0.y, wb);
    fma2(A[2], v1.x, wa); fma2(Bc[2], v1.x, wb);
    fma2(A[3], v1.y, wa); fma2(Bc[3], v1.y, wb);
    fma2(A[4], v2.x, wa); fma2(Bc[4], v2.x, wb);
    fma2(A[5], v2.y, wa); fma2(Bc[5], v2.y, wb);
  }
}

// gemm1: 1 col x 12 tokens (for 256-thread FF phases).
__device__ __forceinline__ void gemm1(const float* __restrict__ sIn,
                                      const float* __restrict__ W, int ldw,
                                      int c0, int k0, int nk, u64t A[6]){
  #pragma unroll 4
  for (int k=k0; k<k0+nk; k++){
    u64t wa = pack2(__ldg(W + (long)k*ldw + c0));
    const ulonglong2* a = (const ulonglong2*)(sIn + k*ST);
    ulonglong2 v0 = a[0], v1 = a[1], v2 = a[2];
    fma2(A[0], v0.x, wa);
    fma2(A[1], v0.y, wa);
    fma2(A[2], v1.x, wa);
    fma2(A[3], v1.y, wa);
    fma2(A[4], v2.x, wa);
    fma2(A[5], v2.y, wa);
  }
}

__device__ __forceinline__ void store6(float* dst, const u64t A[6]){
  #pragma unroll
  for (int p=0;p<6;p++) ((float2*)dst)[p] = *(const float2*)&A[p];
}

// ---------------------------------------------------------------------------
// K2: BOTH transformer layers + conv2/conv3 head fused (R12 structure;
// FF1/FF2 widened to all 256 threads, 1 col/thread).
// grid 1656 (=B*N), block 256. smem arena 46KB.
// ---------------------------------------------------------------------------
#define S_QQ 0
#define S_Q  1280
#define S_K  2560
#define S_V  3840
#define S_X1 5120
#define S_H  6400      // 5120 floats
#define SM_TOT 11520

__global__ void __launch_bounds__(256, 4) k_fused(
    const float* __restrict__ temb,
    const float* __restrict__ Wq, const float* __restrict__ Wk,
    const float* __restrict__ Wv, const float* __restrict__ Wo,
    const float* __restrict__ bo,
    const float* __restrict__ ln1g, const float* __restrict__ ln1b,
    const float* __restrict__ ln2g, const float* __restrict__ ln2b,
    const float* __restrict__ fw1, const float* __restrict__ fb1,
    const float* __restrict__ fw2, const float* __restrict__ fb2,
    const float* __restrict__ lng, const float* __restrict__ lnb,
    const float* __restrict__ w2c, const float* __restrict__ b2c,
    const float* __restrict__ w3c, const float* __restrict__ b3c,
    float* __restrict__ outp)
{
  __shared__ __align__(16) float sm[SM_TOT];

  int tid = threadIdx.x;
  int warp = tid>>5, lane = tid&31;
  long base = (long)blockIdx.x * 768;

  for (int idx=tid; idx<768; idx+=256){
    int e = idx/12, t = idx - e*12;
    sm[S_QQ + e*ST+t] = g_out[base+idx] + __ldg(temb + t*64+e);
  }
  __syncthreads();

  for (int l=0; l<LL; l++){
    const float* Wq_  = Wq  + l*4096;
    const float* Wk_  = Wk  + l*4096;
    const float* Wv_  = Wv  + l*4096;
    const float* Wo_  = Wo  + l*4096;
    const float* bo_  = bo  + l*64;
    const float* ln1g_= ln1g+ l*64;  const float* ln1b_= ln1b+ l*64;
    const float* ln2g_= ln2g+ l*64;  const float* ln2b_= ln2b+ l*64;
    const float* fw1_ = fw1 + l*16384; const float* fb1_ = fb1 + l*256;
    const float* fw2_ = fw2 + l*16384; const float* fb2_ = fb2 + l*64;
    const float* lng_ = lng + l*64;  const float* lnb_ = lnb + l*64;

    // ---- Q,K,V split-k: 192 threads = 3 mats x (32 e2 x 2 kgroups) ----
    if (tid < 192){
      int m  = tid >> 6;
      int kg = (tid >> 5) & 1;
      int e2 = tid & 31;
      const float* W = (m==0 ? Wq_ : (m==1 ? Wk_ : Wv_));
      int bi = m*2 + kg;
      float* pb = (bi < 5) ? (sm + S_H + bi*896) : (sm + S_X1);
      u64t A[6]={0,0,0,0,0,0}, B[6]={0,0,0,0,0,0};
      gemm2(sm + S_QQ, W, 64, e2, e2+32, kg*32, 32, A, B);
      store6(pb + e2*PT, A);
      store6(pb + (e2+32)*PT, B);
    }
    __syncthreads();
    // sum partials -> Q,K,V
    for (int idx=tid; idx<2304; idx+=256){
      int m = idx/768, r = idx - m*768;
      int e = r/12, t = r - e*12;
      const float* p0 = (m*2   < 5) ? (sm + S_H + (m*2  )*896) : (sm + S_X1);
      const float* p1 = (m*2+1 < 5) ? (sm + S_H + (m*2+1)*896) : (sm + S_X1);
      float v = p0[e*PT+t] + p1[e*PT+t];
      float* dst = sm + (m==0 ? S_Q : (m==1 ? S_K : S_V));
      dst[e*ST+t] = v;
    }
    __syncthreads();

    // ---- attention scores: 192 threads, 3 scores each ----
    if (tid < 192){
      int h = tid / 48;
      int rem = tid - h*48;
      int t2 = rem >> 2;
      int sq = (rem & 3) * 3;
      const float* qp = sm + S_Q + (h*16)*ST + t2;
      float q[16];
      #pragma unroll
      for (int d=0; d<16; d++) q[d] = qp[d*ST];
      #pragma unroll
      for (int j=0;j<3;j++){
        int s = sq + j;
        const float* kp = sm + S_K + (h*16)*ST + s;
        float sum=0.f;
        #pragma unroll
        for (int d=0;d<16;d++) sum += q[d]*kp[d*ST];
        sm[S_H + (h*12+t2)*12 + s] = sum*0.25f;
      }
    }
    __syncthreads();
    if (tid < 48){
      float* row = sm + S_H + tid*12;
      float mxv = row[0];
      #pragma unroll
      for (int s=1;s<12;s++) mxv = fmaxf(mxv,row[s]);
      float evv[12]; float sum=0.f;
      #pragma unroll
      for (int s=0;s<12;s++){ evv[s]=__expf(row[s]-mxv); sum+=evv[s]; }
      float inv = 1.f/sum;
      #pragma unroll
      for (int s=0;s<12;s++) row[s]=evv[s]*inv;
    }
    __syncthreads();

    // ---- ctx = att @ V (float4 loads; into S_Q) ----
    for (int idx=tid; idx<768; idx+=256){
      int e = idx/12, t2 = idx - e*12, h = e>>4;
      const float4* a4 = (const float4*)(sm + S_H + (h*12+t2)*12);
      const float4* v4 = (const float4*)(sm + S_V + e*ST);
      float4 a0=a4[0], a1=a4[1], a2=a4[2];
      float4 v0=v4[0], v1=v4[1], v2=v4[2];
      float sum = a0.x*v0.x + a0.y*v0.y + a0.z*v0.z + a0.w*v0.w
                + a1.x*v1.x + a1.y*v1.y + a1.z*v1.z + a1.w*v1.w
                + a2.x*v2.x + a2.y*v2.y + a2.z*v2.z + a2.w*v2.w;
      sm[S_Q + e*ST+t2] = sum;
    }
    __syncthreads();

    // ---- attn_out = ctx @ Wo : 128 threads, 4 kgroups; partials -> S_H ----
    if (tid < 128){
      int kg = tid>>5, e2 = tid&31;
      u64t A[6]={0,0,0,0,0,0}, B[6]={0,0,0,0,0,0};
      gemm2(sm + S_Q, Wo_, 64, e2, e2+32, kg*16, 16, A, B);
      float* pb = sm + S_H + kg*896;
      store6(pb + e2*PT, A);
      store6(pb + (e2+32)*PT, B);
    }
    __syncthreads();

    // ---- LN1 merged with Wo-sum + bias + residual; -> S_X1 ----
    for (int t = warp; t < 12; t += 8){
      int e0 = lane, e1 = lane+32;
      float v0 = sm[S_H+e0*PT+t]+sm[S_H+896+e0*PT+t]+sm[S_H+1792+e0*PT+t]+sm[S_H+2688+e0*PT+t]
               + bo_[e0] + sm[S_QQ+e0*ST+t];
      float v1 = sm[S_H+e1*PT+t]+sm[S_H+896+e1*PT+t]+sm[S_H+1792+e1*PT+t]+sm[S_H+2688+e1*PT+t]
               + bo_[e1] + sm[S_QQ+e1*ST+t];
      float s  = warp_sum(v0+v1);
      float s2 = warp_sum(v0*v0+v1*v1);
      float mean = s*(1.f/64.f);
      float var  = s2*(1.f/64.f) - mean*mean;
      float r = rsqrtf(var + 1e-5f);
      sm[S_X1+e0*ST+t] = (v0-mean)*r*ln1g_[e0] + ln1b_[e0];
      sm[S_X1+e1*ST+t] = (v1-mean)*r*ln1g_[e1] + ln1b_[e1];
    }
    __syncthreads();

    // ---- FF1: 256 threads, 1 col each, full k=64; relu -> S_H ----
    {
      int f = tid;
      u64t A[6]={0,0,0,0,0,0};
      gemm1(sm + S_X1, fw1_, 256, f, 0, 64, A);
      float ba = fb1_[f];
      float* dA = sm + S_H + f*ST;
      #pragma unroll
      for (int p=0;p<6;p++){
        float2 va = *(const float2*)&A[p];
        va.x = fmaxf(va.x+ba,0.f);  va.y = fmaxf(va.y+ba,0.f);
        ((float2*)dA)[p] = va;
      }
    }
    __syncthreads();

    // ---- FF2: 256 threads, 1 col, 4 kgroups of 64; partials -> S_Q ----
    {
      int kg = tid>>6, e = tid&63;
      u64t A[6]={0,0,0,0,0,0};
      gemm1(sm + S_H, fw2_, 64, e, kg*64, 64, A);
      float* pb = sm + S_Q + kg*896;
      store6(pb + e*PT, A);
    }
    __syncthreads();

    // ---- LN2 merged with FF2-sum + bias + residual(X1); -> S_X1 ----
    for (int t = warp; t < 12; t += 8){
      int e0 = lane, e1 = lane+32;
      float v0 = sm[S_Q+e0*PT+t]+sm[S_Q+896+e0*PT+t]+sm[S_Q+1792+e0*PT+t]+sm[S_Q+2688+e0*PT+t]
               + fb2_[e0] + sm[S_X1+e0*ST+t];
      float v1 = sm[S_Q+e1*PT+t]+sm[S_Q+896+e1*PT+t]+sm[S_Q+1792+e1*PT+t]+sm[S_Q+2688+e1*PT+t]
               + fb2_[e1] + sm[S_X1+e1*ST+t];
      float s  = warp_sum(v0+v1);
      float s2 = warp_sum(v0*v0+v1*v1);
      float mean = s*(1.f/64.f);
      float var  = s2*(1.f/64.f) - mean*mean;
      float r = rsqrtf(var + 1e-5f);
      sm[S_X1+e0*ST+t] = (v0-mean)*r*ln2g_[e0] + ln2b_[e0];
      sm[S_X1+e1*ST+t] = (v1-mean)*r*ln2g_[e1] + ln2b_[e1];
    }
    __syncthreads();

    // ---- LN3 merged with residual (QQ - temb) ----
    for (int t = warp; t < 12; t += 8){
      int e0 = lane, e1 = lane+32;
      float te0 = __ldg(temb + t*64+e0), te1 = __ldg(temb + t*64+e1);
      float v0 = sm[S_X1+e0*ST+t] + sm[S_QQ+e0*ST+t] - te0;
      float v1 = sm[S_X1+e1*ST+t] + sm[S_QQ+e1*ST+t] - te1;
      float s  = warp_sum(v0+v1);
      float s2 = warp_sum(v0*v0+v1*v1);
      float mean = s*(1.f/64.f);
      float var  = s2*(1.f/64.f) - mean*mean;
      float r = rsqrtf(var + 1e-5f);
      float o0 = (v0-mean)*r*lng_[e0] + lnb_[e0];
      float o1 = (v1-mean)*r*lng_[e1] + lnb_[e1];
      if (l+1 < LL){
        sm[S_QQ+e0*ST+t] = o0 + te0;
        sm[S_QQ+e1*ST+t] = o1 + te1;
      } else {
        sm[S_K+e0*ST+t] = o0;
        sm[S_K+e1*ST+t] = o1;
      }
    }
    __syncthreads();
  }

  // ---- head: conv2 over t (relu) + conv3 over e. out in S_K ----
  if (tid < 192){
    int o = tid>>4, es = (tid&15)*4;
    float w2row[12];
    #pragma unroll
    for (int t=0;t<12;t++) w2row[t] = __ldg(w2c + o*12 + t);
    float b2v = __ldg(b2c + o);
    float acc = 0.f;
    #pragma unroll
    for (int q=0;q<4;q++){
      int e = es + q;
      const float* rowp = sm + S_K + e*ST;
      float v = b2v;
      #pragma unroll
      for (int t=0;t<12;t++) v += rowp[t]*w2row[t];
      v = fmaxf(v, 0.f);
      acc += v * __ldg(w3c + e);
    }
    #pragma unroll
    for (int off=8; off; off>>=1) acc += __shfl_xor_sync(0xffffffffu, acc, off);
    if ((tid&15)==0) outp[(long)blockIdx.x*12 + o] = acc + __ldg(b3c);
  }
}

// ---------------------------------------------------------------------------
extern "C" void kernel_launch(void* const* d_in, const int* in_sizes, int n_in,
                              void* d_out, int out_size) {
  const float* x       = (const float*)d_in[0];
  const int*   adj     = (const int*)  d_in[1];
  const float* gat_W2  = (const float*)d_in[2];
  const float* gat_a   = (const float*)d_in[3];
  const float* gat_b   = (const float*)d_in[4];
  const float* conv1_w = (const float*)d_in[5];
  const float* conv1_b = (const float*)d_in[6];
  const float* temb    = (const float*)d_in[7];
  const float* Wq      = (const float*)d_in[8];
  const float* Wk      = (const float*)d_in[9];
  const float* Wv      = (const float*)d_in[10];
  const float* Wo      = (const float*)d_in[11];
  const float* bo      = (const float*)d_in[12];
  const float* ln1_g   = (const float*)d_in[13];
  const float* ln1_b   = (const float*)d_in[14];
  const float* ln2_g   = (const float*)d_in[15];
  const float* ln2_b   = (const float*)d_in[16];
  const float* ff_w1   = (const float*)d_in[17];
  const float* ff_b1   = (const float*)d_in[18];
  const float* ff_w2   = (const float*)d_in[19];
  const float* ff_b2   = (const float*)d_in[20];
  const float* lng     = (const float*)d_in[21];
  const float* lnb     = (const float*)d_in[22];
  const float* conv2_w = (const float*)d_in[23];
  const float* conv2_b = (const float*)d_in[24];
  const float* conv3_w = (const float*)d_in[25];
  const float* conv3_b = (const float*)d_in[26];
  float* outp = (float*)d_out;

  dim3 g1(BB, (NV + 1) / 2);
  k_gat<<<g1, 128>>>(x, adj, gat_W2, gat_a, gat_b, conv1_w, conv1_b);

  k_fused<<<BB*NV, 256>>>(temb, Wq, Wk, Wv, Wo, bo,
                          ln1_g, ln1_b, ln2_g, ln2_b,
                          ff_w1, ff_b1, ff_w2, ff_b2,
                          lng, lnb,
                          conv2_w, conv2_b, conv3_w, conv3_b, outp);
}

// round 16
// speedup vs baseline: 1.1274x; 1.0711x over previous
#include <cuda_runtime.h>

#define BB 8
#define NV 207
#define TT 12
#define LL 2
#define NGH 8
#define ALPHA 0.2f
#define NN (NV*NV)
#define ST 20   // k-major stride for activation buffers (floats)
#define PT 14   // stride for partial-sum buffers
#define XR 418  // GAT slab row stride (per t)

typedef unsigned long long u64t;

// scratch: gat output (B*N groups, layout per group: e*12+t)
__device__ float g_out[BB*NV*TT*64];

__device__ __forceinline__ float warp_sum(float v){
  #pragma unroll
  for (int o=16;o;o>>=1) v += __shfl_xor_sync(0xffffffffu, v, o);
  return v;
}
__device__ __forceinline__ u64t pack2(float v){
  u64t r; asm("mov.b64 %0, {%1, %1};" : "=l"(r) : "f"(v)); return r;
}
__device__ __forceinline__ void fma2(u64t &acc, u64t a, u64t b){
  asm("fma.rn.f32x2 %0, %1, %2, %0;" : "+l"(acc) : "l"(a), "l"(b));
}

// ---------------------------------------------------------------------------
// K1: GAT + conv1 (exact R12 winner).
// ---------------------------------------------------------------------------
__global__ void __launch_bounds__(128) k_gat(
    const float* __restrict__ x,      // (B,C,N,T)
    const int*   __restrict__ adj,    // (B,N,N)
    const float* __restrict__ W2,     // (8,4,2)
    const float* __restrict__ ga,     // (8,2)
    const float* __restrict__ gb,     // (8,2)
    const float* __restrict__ w1,     // (4,64)
    const float* __restrict__ b1)     // (64)
{
  __shared__ float xsa[TT*XR];     // [t][2n+c]
  __shared__ int   adjs[2*NV];
  __shared__ float w1s[256];
  __shared__ float b1s[64];

  int b  = blockIdx.x;
  int i0 = blockIdx.y * 2;
  int tid = threadIdx.x;

  const float* xb = x + (long)b*2*NV*TT;
  for (int idx=tid; idx<2*NV*TT; idx+=128){
    int c = idx/(NV*TT); int r = idx - c*NV*TT;
    int n = r/TT, t = r - n*TT;
    xsa[t*XR + 2*n + c] = xb[idx];
  }
  int nrows = (NV - i0) < 2 ? (NV - i0) : 2;
  for (int idx=tid; idx<nrows*NV; idx+=128){
    int ii = idx / NV, j = idx - ii*NV;
    adjs[ii*NV+j] = adj[((long)b*NV + i0+ii)*NV + j];
  }
  for (int idx=tid; idx<256; idx+=128) w1s[idx]=w1[idx];
  if (tid<64) b1s[tid]=b1[tid];
  __syncthreads();

  int warp = tid>>5, lane = tid&31;

  for (int task = warp; task < 24; task += 4){
    int t  = task % 12;
    int ii = task / 12;
    int i  = i0 + ii;
    if (i >= NV) continue;
    const int* arow = adjs + ii*NV;
    const float* xrow = xsa + t*XR;

    int pk[7];
    #pragma unroll
    for (int jj=0; jj<7; jj++){
      int j = jj*32 + lane;
      bool valid = j < NV;
      int jc = valid ? j : 0;
      bool ok = valid && (arow[jc] > 0);
      int r0 = 2*(i*NV + jc);
      int a0 = (r0   < NN) ? (2*i + (jc>=104)) : ((jc>=104) ? 2*jc-207 : 2*jc);
      int a1 = (r0+1 < NN) ? (2*i + (jc>=103)) : ((jc>=103) ? 2*jc-206 : 2*jc+1);
      pk[jj] = a0 | (a1<<9) | ((ok?1:0)<<18) | (jc<<19);
    }

    float acc0=0.f, acc1=0.f;
    #pragma unroll
    for (int hg=0; hg<2; hg++){
      float w2r[4][4][2], ar[4][2];
      #pragma unroll
      for (int hh=0;hh<4;hh++){
        int h = hg*4+hh;
        #pragma unroll
        for (int k=0;k<4;k++){
          w2r[hh][k][0]=__ldg(W2+(h*4+k)*2+0);
          w2r[hh][k][1]=__ldg(W2+(h*4+k)*2+1);
        }
        ar[hh][0]=__ldg(ga+h*2); ar[hh][1]=__ldg(ga+h*2+1);
      }
      float d[4]={0,0,0,0}, n0[4]={0,0,0,0}, n1[4]={0,0,0,0};
      #pragma unroll
      for (int jj=0; jj<7; jj++){
        int p = pk[jj];
        int a0 =  p        & 511;
        int a1 = (p >> 9)  & 511;
        float okf = (float)((p >> 18) & 1);
        int jc = (p >> 19);
        float2 ca = *(const float2*)(xrow + 2*a0);
        float2 cb = *(const float2*)(xrow + 2*a1);
        float2 xj = *(const float2*)(xrow + 2*jc);
        #pragma unroll
        for (int hh=0;hh<4;hh++){
          float we0 = ca.x*w2r[hh][0][0] + ca.y*w2r[hh][1][0] + cb.x*w2r[hh][2][0] + cb.y*w2r[hh][3][0];
          float we1 = ca.x*w2r[hh][0][1] + ca.y*w2r[hh][1][1] + cb.x*w2r[hh][2][1] + cb.y*w2r[hh][3][1];
          we0 = (we0 > 0.f) ? we0 : ALPHA*we0;
          we1 = (we1 > 0.f) ? we1 : ALPHA*we1;
          float e = we0*ar[hh][0] + we1*ar[hh][1];
          float w = okf * __expf(e);
          d[hh]  += w;
          n0[hh] += w*xj.x;
          n1[hh] += w*xj.y;
        }
      }
      #pragma unroll
      for (int off=16; off; off>>=1){
        #pragma unroll
        for (int hh=0;hh<4;hh++){
          d[hh]  += __shfl_xor_sync(0xffffffffu, d[hh],  off);
          n0[hh] += __shfl_xor_sync(0xffffffffu, n0[hh], off);
          n1[hh] += __shfl_xor_sync(0xffffffffu, n1[hh], off);
        }
      }
      #pragma unroll
      for (int hh=0;hh<4;hh++){
        int h = hg*4+hh;
        float inv = 1.0f/d[hh];
        float z0 = n0[hh]*inv + __ldg(gb+h*2+0);
        float z1 = n1[hh]*inv + __ldg(gb+h*2+1);
        acc0 += 1.f - __fdividef(2.f, __expf(2.f*z0)+1.f);
        acc1 += 1.f - __fdividef(2.f, __expf(2.f*z1)+1.f);
      }
    }
    acc0 *= 0.125f; acc1 *= 0.125f;

    float xi0 = xrow[2*i], xi1 = xrow[2*i+1];
    long obase = (long)(b*NV + i)*768;
    #pragma unroll
    for (int r=0;r<2;r++){
      int e = lane + r*32;
      g_out[obase + e*12 + t] = xi0*w1s[e] + xi1*w1s[64+e]
                              + acc0*w1s[128+e] + acc1*w1s[192+e] + b1s[e];
    }
  }
}

// ---------------------------------------------------------------------------
// gemm2: 2 cols x 12 tokens (R12 winner shape).
// ---------------------------------------------------------------------------
__device__ __forceinline__ void gemm2(const float* __restrict__ sIn,
                                      const float* __restrict__ W, int ldw,
                                      int c0, int c1, int k0, int nk,
                                      u64t A[6], u64t Bc[6]){
  #pragma unroll 4
  for (int k=k0; k<k0+nk; k++){
    const float* wr = W + (long)k*ldw;
    u64t wa = pack2(__ldg(wr+c0));
    u64t wb = pack2(__ldg(wr+c1));
    const ulonglong2* a = (const ulonglong2*)(sIn + k*ST);
    ulonglong2 v0 = a[0], v1 = a[1], v2 = a[2];
    fma2(A[0], v0.x, wa); fma2(Bc[0], v0.x, wb);
    fma2(A[1], v0.y, wa); fma2(Bc[1], v0.y, wb);
    fma2(A[2], v1.x, wa); fma2(Bc[2], v1.x, wb);
    fma2(A[3], v1.y, wa); fma2(Bc[3], v1.y, wb);
    fma2(A[4], v2.x, wa); fma2(Bc[4], v2.x, wb);
    fma2(A[5], v2.y, wa); fma2(Bc[5], v2.y, wb);
  }
}

// gemm1: 1 col x 12 tokens (QKV direct, full k; per-lane coalesced LDG).
__device__ __forceinline__ void gemm1(const float* __restrict__ sIn,
                                      const float* __restrict__ W, int ldw,
                                      int c0, int k0, int nk, u64t A[6]){
  #pragma unroll 4
  for (int k=k0; k<k0+nk; k++){
    u64t wa = pack2(__ldg(W + (long)k*ldw + c0));
    const ulonglong2* a = (const ulonglong2*)(sIn + k*ST);
    ulonglong2 v0 = a[0], v1 = a[1], v2 = a[2];
    fma2(A[0], v0.x, wa);
    fma2(A[1], v0.y, wa);
    fma2(A[2], v1.x, wa);
    fma2(A[3], v1.y, wa);
    fma2(A[4], v2.x, wa);
    fma2(A[5], v2.y, wa);
  }
}

__device__ __forceinline__ void store6(float* dst, const u64t A[6]){
  #pragma unroll
  for (int p=0;p<6;p++) ((float2*)dst)[p] = *(const float2*)&A[p];
}

// ---------------------------------------------------------------------------
// K2: BOTH transformer layers + conv2/conv3 head fused (R12 structure;
// QKV direct-store, softmax without max pass).
// grid 1656 (=B*N), block 256. smem arena 46KB.
// ---------------------------------------------------------------------------
#define S_QQ 0
#define S_Q  1280
#define S_K  2560
#define S_V  3840
#define S_X1 5120
#define S_H  6400      // 5120 floats
#define SM_TOT 11520

__global__ void __launch_bounds__(256, 4) k_fused(
    const float* __restrict__ temb,
    const float* __restrict__ Wq, const float* __restrict__ Wk,
    const float* __restrict__ Wv, const float* __restrict__ Wo,
    const float* __restrict__ bo,
    const float* __restrict__ ln1g, const float* __restrict__ ln1b,
    const float* __restrict__ ln2g, const float* __restrict__ ln2b,
    const float* __restrict__ fw1, const float* __restrict__ fb1,
    const float* __restrict__ fw2, const float* __restrict__ fb2,
    const float* __restrict__ lng, const float* __restrict__ lnb,
    const float* __restrict__ w2c, const float* __restrict__ b2c,
    const float* __restrict__ w3c, const float* __restrict__ b3c,
    float* __restrict__ outp)
{
  __shared__ __align__(16) float sm[SM_TOT];

  int tid = threadIdx.x;
  int warp = tid>>5, lane = tid&31;
  long base = (long)blockIdx.x * 768;

  for (int idx=tid; idx<768; idx+=256){
    int e = idx/12, t = idx - e*12;
    sm[S_QQ + e*ST+t] = g_out[base+idx] + __ldg(temb + t*64+e);
  }
  __syncthreads();

  for (int l=0; l<LL; l++){
    const float* Wq_  = Wq  + l*4096;
    const float* Wk_  = Wk  + l*4096;
    const float* Wv_  = Wv  + l*4096;
    const float* Wo_  = Wo  + l*4096;
    const float* bo_  = bo  + l*64;
    const float* ln1g_= ln1g+ l*64;  const float* ln1b_= ln1b+ l*64;
    const float* ln2g_= ln2g+ l*64;  const float* ln2b_= ln2b+ l*64;
    const float* fw1_ = fw1 + l*16384; const float* fb1_ = fb1 + l*256;
    const float* fw2_ = fw2 + l*16384; const float* fb2_ = fb2 + l*64;
    const float* lng_ = lng + l*64;  const float* lnb_ = lnb + l*64;

    // ---- Q,K,V: 192 threads = 3 mats x 64 cols, 1 col/thread, full k,
    //      direct store (no partials, no sum pass, one fewer barrier) ----
    if (tid < 192){
      int m = tid >> 6, e = tid & 63;
      const float* W = (m==0 ? Wq_ : (m==1 ? Wk_ : Wv_));
      float* dst = sm + (m==0 ? S_Q : (m==1 ? S_K : S_V));
      u64t A[6]={0,0,0,0,0,0};
      gemm1(sm + S_QQ, W, 64, e, 0, 64, A);
      store6(dst + e*ST, A);
    }
    __syncthreads();

    // ---- attention scores: 192 threads, 3 scores each ----
    if (tid < 192){
      int h = tid / 48;
      int rem = tid - h*48;
      int t2 = rem >> 2;
      int sq = (rem & 3) * 3;
      const float* qp = sm + S_Q + (h*16)*ST + t2;
      float q[16];
      #pragma unroll
      for (int d=0; d<16; d++) q[d] = qp[d*ST];
      #pragma unroll
      for (int j=0;j<3;j++){
        int s = sq + j;
        const float* kp = sm + S_K + (h*16)*ST + s;
        float sum=0.f;
        #pragma unroll
        for (int d=0;d<16;d++) sum += q[d]*kp[d*ST];
        sm[S_H + (h*12+t2)*12 + s] = sum*0.25f;
      }
    }
    __syncthreads();
    // softmax, no max pass (scores O(1), fp32-safe)
    if (tid < 48){
      float* row = sm + S_H + tid*12;
      float evv[12]; float sum=0.f;
      #pragma unroll
      for (int s=0;s<12;s++){ evv[s]=__expf(row[s]); sum+=evv[s]; }
      float inv = 1.f/sum;
      #pragma unroll
      for (int s=0;s<12;s++) row[s]=evv[s]*inv;
    }
    __syncthreads();

    // ---- ctx = att @ V (float4 loads; into S_Q) ----
    for (int idx=tid; idx<768; idx+=256){
      int e = idx/12, t2 = idx - e*12, h = e>>4;
      const float4* a4 = (const float4*)(sm + S_H + (h*12+t2)*12);
      const float4* v4 = (const float4*)(sm + S_V + e*ST);
      float4 a0=a4[0], a1=a4[1], a2=a4[2];
      float4 v0=v4[0], v1=v4[1], v2=v4[2];
      float sum = a0.x*v0.x + a0.y*v0.y + a0.z*v0.z + a0.w*v0.w
                + a1.x*v1.x + a1.y*v1.y + a1.z*v1.z + a1.w*v1.w
                + a2.x*v2.x + a2.y*v2.y + a2.z*v2.z + a2.w*v2.w;
      sm[S_Q + e*ST+t2] = sum;
    }
    __syncthreads();

    // ---- attn_out = ctx @ Wo : 128 threads, 4 kgroups; partials -> S_H ----
    if (tid < 128){
      int kg = tid>>5, e2 = tid&31;
      u64t A[6]={0,0,0,0,0,0}, B[6]={0,0,0,0,0,0};
      gemm2(sm + S_Q, Wo_, 64, e2, e2+32, kg*16, 16, A, B);
      float* pb = sm + S_H + kg*896;
      store6(pb + e2*PT, A);
      store6(pb + (e2+32)*PT, B);
    }
    __syncthreads();

    // ---- LN1 merged with Wo-sum + bias + residual; -> S_X1 ----
    for (int t = warp; t < 12; t += 8){
      int e0 = lane, e1 = lane+32;
      float v0 = sm[S_H+e0*PT+t]+sm[S_H+896+e0*PT+t]+sm[S_H+1792+e0*PT+t]+sm[S_H+2688+e0*PT+t]
               + bo_[e0] + sm[S_QQ+e0*ST+t];
      float v1 = sm[S_H+e1*PT+t]+sm[S_H+896+e1*PT+t]+sm[S_H+1792+e1*PT+t]+sm[S_H+2688+e1*PT+t]
               + bo_[e1] + sm[S_QQ+e1*ST+t];
      float s  = warp_sum(v0+v1);
      float s2 = warp_sum(v0*v0+v1*v1);
      float mean = s*(1.f/64.f);
      float var  = s2*(1.f/64.f) - mean*mean;
      float r = rsqrtf(var + 1e-5f);
      sm[S_X1+e0*ST+t] = (v0-mean)*r*ln1g_[e0] + ln1b_[e0];
      sm[S_X1+e1*ST+t] = (v1-mean)*r*ln1g_[e1] + ln1b_[e1];
    }
    __syncthreads();

    // ---- FF1: 128 threads, cols (f, f+128), k=64; relu -> S_H ----
    if (tid < 128){
      int f = tid;
      u64t A[6]={0,0,0,0,0,0}, B[6]={0,0,0,0,0,0};
      gemm2(sm + S_X1, fw1_, 256, f, f+128, 0, 64, A, B);
      float ba = fb1_[f], bb2 = fb1_[f+128];
      float* dA = sm + S_H + f*ST;
      float* dB = sm + S_H + (f+128)*ST;
      #pragma unroll
      for (int p=0;p<6;p++){
        float2 va = *(const float2*)&A[p];
        float2 vb = *(const float2*)&B[p];
        va.x = fmaxf(va.x+ba,0.f);  va.y = fmaxf(va.y+ba,0.f);
        vb.x = fmaxf(vb.x+bb2,0.f); vb.y = fmaxf(vb.y+bb2,0.f);
        ((float2*)dA)[p] = va;
        ((float2*)dB)[p] = vb;
      }
    }
    __syncthreads();

    // ---- FF2: 128 threads, 4 kgroups of 64; partials -> S_Q region ----
    if (tid < 128){
      int kg = tid>>5, e2 = tid&31;
      u64t A[6]={0,0,0,0,0,0}, B[6]={0,0,0,0,0,0};
      gemm2(sm + S_H, fw2_, 64, e2, e2+32, kg*64, 64, A, B);
      float* pb = sm + S_Q + kg*896;
      store6(pb + e2*PT, A);
      store6(pb + (e2+32)*PT, B);
    }
    __syncthreads();

    // ---- LN2 merged with FF2-sum + bias + residual(X1); -> S_X1 ----
    for (int t = warp; t < 12; t += 8){
      int e0 = lane, e1 = lane+32;
      float v0 = sm[S_Q+e0*PT+t]+sm[S_Q+896+e0*PT+t]+sm[S_Q+1792+e0*PT+t]+sm[S_Q+2688+e0*PT+t]
               + fb2_[e0] + sm[S_X1+e0*ST+t];
      float v1 = sm[S_Q+e1*PT+t]+sm[S_Q+896+e1*PT+t]+sm[S_Q+1792+e1*PT+t]+sm[S_Q+2688+e1*PT+t]
               + fb2_[e1] + sm[S_X1+e1*ST+t];
      float s  = warp_sum(v0+v1);
      float s2 = warp_sum(v0*v0+v1*v1);
      float mean = s*(1.f/64.f);
      float var  = s2*(1.f/64.f) - mean*mean;
      float r = rsqrtf(var + 1e-5f);
      sm[S_X1+e0*ST+t] = (v0-mean)*r*ln2g_[e0] + ln2b_[e0];
      sm[S_X1+e1*ST+t] = (v1-mean)*r*ln2g_[e1] + ln2b_[e1];
    }
    __syncthreads();

    // ---- LN3 merged with residual (QQ - temb) ----
    for (int t = warp; t < 12; t += 8){
      int e0 = lane, e1 = lane+32;
      float te0 = __ldg(temb + t*64+e0), te1 = __ldg(temb + t*64+e1);
      float v0 = sm[S_X1+e0*ST+t] + sm[S_QQ+e0*ST+t] - te0;
      float v1 = sm[S_X1+e1*ST+t] + sm[S_QQ+e1*ST+t] - te1;
      float s  = warp_sum(v0+v1);
      float s2 = warp_sum(v0*v0+v1*v1);
      float mean = s*(1.f/64.f);
      float var  = s2*(1.f/64.f) - mean*mean;
      float r = rsqrtf(var + 1e-5f);
      float o0 = (v0-mean)*r*lng_[e0] + lnb_[e0];
      float o1 = (v1-mean)*r*lng_[e1] + lnb_[e1];
      if (l+1 < LL){
        sm[S_QQ+e0*ST+t] = o0 + te0;
        sm[S_QQ+e1*ST+t] = o1 + te1;
      } else {
        sm[S_K+e0*ST+t] = o0;
        sm[S_K+e1*ST+t] = o1;
      }
    }
    __syncthreads();
  }

  // ---- head: conv2 over t (relu) + conv3 over e. out in S_K ----
  if (tid < 192){
    int o = tid>>4, es = (tid&15)*4;
    float w2row[12];
    #pragma unroll
    for (int t=0;t<12;t++) w2row[t] = __ldg(w2c + o*12 + t);
    float b2v = __ldg(b2c + o);
    float acc = 0.f;
    #pragma unroll
    for (int q=0;q<4;q++){
      int e = es + q;
      const float* rowp = sm + S_K + e*ST;
      float v = b2v;
      #pragma unroll
      for (int t=0;t<12;t++) v += rowp[t]*w2row[t];
      v = fmaxf(v, 0.f);
      acc += v * __ldg(w3c + e);
    }
    #pragma unroll
    for (int off=8; off; off>>=1) acc += __shfl_xor_sync(0xffffffffu, acc, off);
    if ((tid&15)==0) outp[(long)blockIdx.x*12 + o] = acc + __ldg(b3c);
  }
}

// ---------------------------------------------------------------------------
extern "C" void kernel_launch(void* const* d_in, const int* in_sizes, int n_in,
                              void* d_out, int out_size) {
  const float* x       = (const float*)d_in[0];
  const int*   adj     = (const int*)  d_in[1];
  const float* gat_W2  = (const float*)d_in[2];
  const float* gat_a   = (const float*)d_in[3];
  const float* gat_b   = (const float*)d_in[4];
  const float* conv1_w = (const float*)d_in[5];
  const float* conv1_b = (const float*)d_in[6];
  const float* temb    = (const float*)d_in[7];
  const float* Wq      = (const float*)d_in[8];
  const float* Wk      = (const float*)d_in[9];
  const float* Wv      = (const float*)d_in[10];
  const float* Wo      = (const float*)d_in[11];
  const float* bo      = (const float*)d_in[12];
  const float* ln1_g   = (const float*)d_in[13];
  const float* ln1_b   = (const float*)d_in[14];
  const float* ln2_g   = (const float*)d_in[15];
  const float* ln2_b   = (const float*)d_in[16];
  const float* ff_w1   = (const float*)d_in[17];
  const float* ff_b1   = (const float*)d_in[18];
  const float* ff_w2   = (const float*)d_in[19];
  const float* ff_b2   = (const float*)d_in[20];
  const float* lng     = (const float*)d_in[21];
  const float* lnb     = (const float*)d_in[22];
  const float* conv2_w = (const float*)d_in[23];
  const float* conv2_b = (const float*)d_in[24];
  const float* conv3_w = (const float*)d_in[25];
  const float* conv3_b = (const float*)d_in[26];
  float* outp = (float*)d_out;

  dim3 g1(BB, (NV + 1) / 2);
  k_gat<<<g1, 128>>>(x, adj, gat_W2, gat_a, gat_b, conv1_w, conv1_b);

  k_fused<<<BB*NV, 256>>>(temb, Wq, Wk, Wv, Wo, bo,
                          ln1_g, ln1_b, ln2_g, ln2_b,
                          ff_w1, ff_b1, ff_w2, ff_b2,
                          lng, lnb,
                          conv2_w, conv2_b, conv3_w, conv3_b, outp);
}

// round 17
// speedup vs baseline: 1.1423x; 1.0133x over previous
#include <cuda_runtime.h>

#define BB 8
#define NV 207
#define TT 12
#define LL 2
#define NGH 8
#define ALPHA 0.2f
#define NN (NV*NV)
#define ST 20   // k-major stride for activation buffers (floats)
#define PT 14   // stride for partial-sum buffers
#define XR 418  // GAT slab row stride (per t)

typedef unsigned long long u64t;

// scratch: gat output (B*N groups, layout per group: e*12+t)
__device__ float g_out[BB*NV*TT*64];

__device__ __forceinline__ float warp_sum(float v){
  #pragma unroll
  for (int o=16;o;o>>=1) v += __shfl_xor_sync(0xffffffffu, v, o);
  return v;
}
__device__ __forceinline__ u64t pack2(float v){
  u64t r; asm("mov.b64 %0, {%1, %1};" : "=l"(r) : "f"(v)); return r;
}
__device__ __forceinline__ void fma2(u64t &acc, u64t a, u64t b){
  asm("fma.rn.f32x2 %0, %1, %2, %0;" : "+l"(acc) : "l"(a), "l"(b));
}

// ---------------------------------------------------------------------------
// K1: GAT + conv1 (exact R12 winner).
// ---------------------------------------------------------------------------
__global__ void __launch_bounds__(128) k_gat(
    const float* __restrict__ x,      // (B,C,N,T)
    const int*   __restrict__ adj,    // (B,N,N)
    const float* __restrict__ W2,     // (8,4,2)
    const float* __restrict__ ga,     // (8,2)
    const float* __restrict__ gb,     // (8,2)
    const float* __restrict__ w1,     // (4,64)
    const float* __restrict__ b1)     // (64)
{
  __shared__ float xsa[TT*XR];     // [t][2n+c]
  __shared__ int   adjs[2*NV];
  __shared__ float w1s[256];
  __shared__ float b1s[64];

  int b  = blockIdx.x;
  int i0 = blockIdx.y * 2;
  int tid = threadIdx.x;

  const float* xb = x + (long)b*2*NV*TT;
  for (int idx=tid; idx<2*NV*TT; idx+=128){
    int c = idx/(NV*TT); int r = idx - c*NV*TT;
    int n = r/TT, t = r - n*TT;
    xsa[t*XR + 2*n + c] = xb[idx];
  }
  int nrows = (NV - i0) < 2 ? (NV - i0) : 2;
  for (int idx=tid; idx<nrows*NV; idx+=128){
    int ii = idx / NV, j = idx - ii*NV;
    adjs[ii*NV+j] = adj[((long)b*NV + i0+ii)*NV + j];
  }
  for (int idx=tid; idx<256; idx+=128) w1s[idx]=w1[idx];
  if (tid<64) b1s[tid]=b1[tid];
  __syncthreads();

  int warp = tid>>5, lane = tid&31;

  for (int task = warp; task < 24; task += 4){
    int t  = task % 12;
    int ii = task / 12;
    int i  = i0 + ii;
    if (i >= NV) continue;
    const int* arow = adjs + ii*NV;
    const float* xrow = xsa + t*XR;

    int pk[7];
    #pragma unroll
    for (int jj=0; jj<7; jj++){
      int j = jj*32 + lane;
      bool valid = j < NV;
      int jc = valid ? j : 0;
      bool ok = valid && (arow[jc] > 0);
      int r0 = 2*(i*NV + jc);
      int a0 = (r0   < NN) ? (2*i + (jc>=104)) : ((jc>=104) ? 2*jc-207 : 2*jc);
      int a1 = (r0+1 < NN) ? (2*i + (jc>=103)) : ((jc>=103) ? 2*jc-206 : 2*jc+1);
      pk[jj] = a0 | (a1<<9) | ((ok?1:0)<<18) | (jc<<19);
    }

    float acc0=0.f, acc1=0.f;
    #pragma unroll
    for (int hg=0; hg<2; hg++){
      float w2r[4][4][2], ar[4][2];
      #pragma unroll
      for (int hh=0;hh<4;hh++){
        int h = hg*4+hh;
        #pragma unroll
        for (int k=0;k<4;k++){
          w2r[hh][k][0]=__ldg(W2+(h*4+k)*2+0);
          w2r[hh][k][1]=__ldg(W2+(h*4+k)*2+1);
        }
        ar[hh][0]=__ldg(ga+h*2); ar[hh][1]=__ldg(ga+h*2+1);
      }
      float d[4]={0,0,0,0}, n0[4]={0,0,0,0}, n1[4]={0,0,0,0};
      #pragma unroll
      for (int jj=0; jj<7; jj++){
        int p = pk[jj];
        int a0 =  p        & 511;
        int a1 = (p >> 9)  & 511;
        float okf = (float)((p >> 18) & 1);
        int jc = (p >> 19);
        float2 ca = *(const float2*)(xrow + 2*a0);
        float2 cb = *(const float2*)(xrow + 2*a1);
        float2 xj = *(const float2*)(xrow + 2*jc);
        #pragma unroll
        for (int hh=0;hh<4;hh++){
          float we0 = ca.x*w2r[hh][0][0] + ca.y*w2r[hh][1][0] + cb.x*w2r[hh][2][0] + cb.y*w2r[hh][3][0];
          float we1 = ca.x*w2r[hh][0][1] + ca.y*w2r[hh][1][1] + cb.x*w2r[hh][2][1] + cb.y*w2r[hh][3][1];
          we0 = (we0 > 0.f) ? we0 : ALPHA*we0;
          we1 = (we1 > 0.f) ? we1 : ALPHA*we1;
          float e = we0*ar[hh][0] + we1*ar[hh][1];
          float w = okf * __expf(e);
          d[hh]  += w;
          n0[hh] += w*xj.x;
          n1[hh] += w*xj.y;
        }
      }
      #pragma unroll
      for (int off=16; off; off>>=1){
        #pragma unroll
        for (int hh=0;hh<4;hh++){
          d[hh]  += __shfl_xor_sync(0xffffffffu, d[hh],  off);
          n0[hh] += __shfl_xor_sync(0xffffffffu, n0[hh], off);
          n1[hh] += __shfl_xor_sync(0xffffffffu, n1[hh], off);
        }
      }
      #pragma unroll
      for (int hh=0;hh<4;hh++){
        int h = hg*4+hh;
        float inv = 1.0f/d[hh];
        float z0 = n0[hh]*inv + __ldg(gb+h*2+0);
        float z1 = n1[hh]*inv + __ldg(gb+h*2+1);
        acc0 += 1.f - __fdividef(2.f, __expf(2.f*z0)+1.f);
        acc1 += 1.f - __fdividef(2.f, __expf(2.f*z1)+1.f);
      }
    }
    acc0 *= 0.125f; acc1 *= 0.125f;

    float xi0 = xrow[2*i], xi1 = xrow[2*i+1];
    long obase = (long)(b*NV + i)*768;
    #pragma unroll
    for (int r=0;r<2;r++){
      int e = lane + r*32;
      g_out[obase + e*12 + t] = xi0*w1s[e] + xi1*w1s[64+e]
                              + acc0*w1s[128+e] + acc1*w1s[192+e] + b1s[e];
    }
  }
}

// ---------------------------------------------------------------------------
// gemm2: 2 cols x 12 tokens (R12 winner shape).
// ---------------------------------------------------------------------------
__device__ __forceinline__ void gemm2(const float* __restrict__ sIn,
                                      const float* __restrict__ W, int ldw,
                                      int c0, int c1, int k0, int nk,
                                      u64t A[6], u64t Bc[6]){
  #pragma unroll 4
  for (int k=k0; k<k0+nk; k++){
    const float* wr = W + (long)k*ldw;
    u64t wa = pack2(__ldg(wr+c0));
    u64t wb = pack2(__ldg(wr+c1));
    const ulonglong2* a = (const ulonglong2*)(sIn + k*ST);
    ulonglong2 v0 = a[0], v1 = a[1], v2 = a[2];
    fma2(A[0], v0.x, wa); fma2(Bc[0], v0.x, wb);
    fma2(A[1], v0.y, wa); fma2(Bc[1], v0.y, wb);
    fma2(A[2], v1.x, wa); fma2(Bc[2], v1.x, wb);
    fma2(A[3], v1.y, wa); fma2(Bc[3], v1.y, wb);
    fma2(A[4], v2.x, wa); fma2(Bc[4], v2.x, wb);
    fma2(A[5], v2.y, wa); fma2(Bc[5], v2.y, wb);
  }
}

__device__ __forceinline__ void store6(float* dst, const u64t A[6]){
  #pragma unroll
  for (int p=0;p<6;p++) ((float2*)dst)[p] = *(const float2*)&A[p];
}

// ---------------------------------------------------------------------------
// K2: BOTH transformer layers + conv2/conv3 head fused (exact R12 body,
// softmax max-pass removed).
// grid 1656 (=B*N), block 256. smem arena 46KB.
// ---------------------------------------------------------------------------
#define S_QQ 0
#define S_Q  1280
#define S_K  2560
#define S_V  3840
#define S_X1 5120
#define S_H  6400      // 5120 floats
#define SM_TOT 11520

__global__ void __launch_bounds__(256, 4) k_fused(
    const float* __restrict__ temb,
    const float* __restrict__ Wq, const float* __restrict__ Wk,
    const float* __restrict__ Wv, const float* __restrict__ Wo,
    const float* __restrict__ bo,
    const float* __restrict__ ln1g, const float* __restrict__ ln1b,
    const float* __restrict__ ln2g, const float* __restrict__ ln2b,
    const float* __restrict__ fw1, const float* __restrict__ fb1,
    const float* __restrict__ fw2, const float* __restrict__ fb2,
    const float* __restrict__ lng, const float* __restrict__ lnb,
    const float* __restrict__ w2c, const float* __restrict__ b2c,
    const float* __restrict__ w3c, const float* __restrict__ b3c,
    float* __restrict__ outp)
{
  __shared__ __align__(16) float sm[SM_TOT];

  int tid = threadIdx.x;
  int warp = tid>>5, lane = tid&31;
  long base = (long)blockIdx.x * 768;

  for (int idx=tid; idx<768; idx+=256){
    int e = idx/12, t = idx - e*12;
    sm[S_QQ + e*ST+t] = g_out[base+idx] + __ldg(temb + t*64+e);
  }
  __syncthreads();

  for (int l=0; l<LL; l++){
    const float* Wq_  = Wq  + l*4096;
    const float* Wk_  = Wk  + l*4096;
    const float* Wv_  = Wv  + l*4096;
    const float* Wo_  = Wo  + l*4096;
    const float* bo_  = bo  + l*64;
    const float* ln1g_= ln1g+ l*64;  const float* ln1b_= ln1b+ l*64;
    const float* ln2g_= ln2g+ l*64;  const float* ln2b_= ln2b+ l*64;
    const float* fw1_ = fw1 + l*16384; const float* fb1_ = fb1 + l*256;
    const float* fw2_ = fw2 + l*16384; const float* fb2_ = fb2 + l*64;
    const float* lng_ = lng + l*64;  const float* lnb_ = lnb + l*64;

    // ---- Q,K,V split-k: 192 threads = 3 mats x (32 e2 x 2 kgroups) ----
    if (tid < 192){
      int m  = tid >> 6;
      int kg = (tid >> 5) & 1;
      int e2 = tid & 31;
      const float* W = (m==0 ? Wq_ : (m==1 ? Wk_ : Wv_));
      int bi = m*2 + kg;
      float* pb = (bi < 5) ? (sm + S_H + bi*896) : (sm + S_X1);
      u64t A[6]={0,0,0,0,0,0}, B[6]={0,0,0,0,0,0};
      gemm2(sm + S_QQ, W, 64, e2, e2+32, kg*32, 32, A, B);
      store6(pb + e2*PT, A);
      store6(pb + (e2+32)*PT, B);
    }
    __syncthreads();
    // sum partials -> Q,K,V
    for (int idx=tid; idx<2304; idx+=256){
      int m = idx/768, r = idx - m*768;
      int e = r/12, t = r - e*12;
      const float* p0 = (m*2   < 5) ? (sm + S_H + (m*2  )*896) : (sm + S_X1);
      const float* p1 = (m*2+1 < 5) ? (sm + S_H + (m*2+1)*896) : (sm + S_X1);
      float v = p0[e*PT+t] + p1[e*PT+t];
      float* dst = sm + (m==0 ? S_Q : (m==1 ? S_K : S_V));
      dst[e*ST+t] = v;
    }
    __syncthreads();

    // ---- attention scores: 192 threads, 3 scores each ----
    if (tid < 192){
      int h = tid / 48;
      int rem = tid - h*48;
      int t2 = rem >> 2;
      int sq = (rem & 3) * 3;
      const float* qp = sm + S_Q + (h*16)*ST + t2;
      float q[16];
      #pragma unroll
      for (int d=0; d<16; d++) q[d] = qp[d*ST];
      #pragma unroll
      for (int j=0;j<3;j++){
        int s = sq + j;
        const float* kp = sm + S_K + (h*16)*ST + s;
        float sum=0.f;
        #pragma unroll
        for (int d=0;d<16;d++) sum += q[d]*kp[d*ST];
        sm[S_H + (h*12+t2)*12 + s] = sum*0.25f;
      }
    }
    __syncthreads();
    // softmax, no max pass (scores O(1) post-LN, fp32-safe)
    if (tid < 48){
      float* row = sm + S_H + tid*12;
      float evv[12]; float sum=0.f;
      #pragma unroll
      for (int s=0;s<12;s++){ evv[s]=__expf(row[s]); sum+=evv[s]; }
      float inv = 1.f/sum;
      #pragma unroll
      for (int s=0;s<12;s++) row[s]=evv[s]*inv;
    }
    __syncthreads();

    // ---- ctx = att @ V (float4 loads; into S_Q) ----
    for (int idx=tid; idx<768; idx+=256){
      int e = idx/12, t2 = idx - e*12, h = e>>4;
      const float4* a4 = (const float4*)(sm + S_H + (h*12+t2)*12);
      const float4* v4 = (const float4*)(sm + S_V + e*ST);
      float4 a0=a4[0], a1=a4[1], a2=a4[2];
      float4 v0=v4[0], v1=v4[1], v2=v4[2];
      float sum = a0.x*v0.x + a0.y*v0.y + a0.z*v0.z + a0.w*v0.w
                + a1.x*v1.x + a1.y*v1.y + a1.z*v1.z + a1.w*v1.w
                + a2.x*v2.x + a2.y*v2.y + a2.z*v2.z + a2.w*v2.w;
      sm[S_Q + e*ST+t2] = sum;
    }
    __syncthreads();

    // ---- attn_out = ctx @ Wo : 128 threads, 4 kgroups; partials -> S_H ----
    if (tid < 128){
      int kg = tid>>5, e2 = tid&31;
      u64t A[6]={0,0,0,0,0,0}, B[6]={0,0,0,0,0,0};
      gemm2(sm + S_Q, Wo_, 64, e2, e2+32, kg*16, 16, A, B);
      float* pb = sm + S_H + kg*896;
      store6(pb + e2*PT, A);
      store6(pb + (e2+32)*PT, B);
    }
    __syncthreads();

    // ---- LN1 merged with Wo-sum + bias + residual; -> S_X1 ----
    for (int t = warp; t < 12; t += 8){
      int e0 = lane, e1 = lane+32;
      float v0 = sm[S_H+e0*PT+t]+sm[S_H+896+e0*PT+t]+sm[S_H+1792+e0*PT+t]+sm[S_H+2688+e0*PT+t]
               + bo_[e0] + sm[S_QQ+e0*ST+t];
      float v1 = sm[S_H+e1*PT+t]+sm[S_H+896+e1*PT+t]+sm[S_H+1792+e1*PT+t]+sm[S_H+2688+e1*PT+t]
               + bo_[e1] + sm[S_QQ+e1*ST+t];
      float s  = warp_sum(v0+v1);
      float s2 = warp_sum(v0*v0+v1*v1);
      float mean = s*(1.f/64.f);
      float var  = s2*(1.f/64.f) - mean*mean;
      float r = rsqrtf(var + 1e-5f);
      sm[S_X1+e0*ST+t] = (v0-mean)*r*ln1g_[e0] + ln1b_[e0];
      sm[S_X1+e1*ST+t] = (v1-mean)*r*ln1g_[e1] + ln1b_[e1];
    }
    __syncthreads();

    // ---- FF1: 128 threads, cols (f, f+128), k=64; relu -> S_H ----
    if (tid < 128){
      int f = tid;
      u64t A[6]={0,0,0,0,0,0}, B[6]={0,0,0,0,0,0};
      gemm2(sm + S_X1, fw1_, 256, f, f+128, 0, 64, A, B);
      float ba = fb1_[f], bb2 = fb1_[f+128];
      float* dA = sm + S_H + f*ST;
      float* dB = sm + S_H + (f+128)*ST;
      #pragma unroll
      for (int p=0;p<6;p++){
        float2 va = *(const float2*)&A[p];
        float2 vb = *(const float2*)&B[p];
        va.x = fmaxf(va.x+ba,0.f);  va.y = fmaxf(va.y+ba,0.f);
        vb.x = fmaxf(vb.x+bb2,0.f); vb.y = fmaxf(vb.y+bb2,0.f);
        ((float2*)dA)[p] = va;
        ((float2*)dB)[p] = vb;
      }
    }
    __syncthreads();

    // ---- FF2: 128 threads, 4 kgroups of 64; partials -> S_Q region ----
    if (tid < 128){
      int kg = tid>>5, e2 = tid&31;
      u64t A[6]={0,0,0,0,0,0}, B[6]={0,0,0,0,0,0};
      gemm2(sm + S_H, fw2_, 64, e2, e2+32, kg*64, 64, A, B);
      float* pb = sm + S_Q + kg*896;
      store6(pb + e2*PT, A);
      store6(pb + (e2+32)*PT, B);
    }
    __syncthreads();

    // ---- LN2 merged with FF2-sum + bias + residual(X1); -> S_X1 ----
    for (int t = warp; t < 12; t += 8){
      int e0 = lane, e1 = lane+32;
      float v0 = sm[S_Q+e0*PT+t]+sm[S_Q+896+e0*PT+t]+sm[S_Q+1792+e0*PT+t]+sm[S_Q+2688+e0*PT+t]
               + fb2_[e0] + sm[S_X1+e0*ST+t];
      float v1 = sm[S_Q+e1*PT+t]+sm[S_Q+896+e1*PT+t]+sm[S_Q+1792+e1*PT+t]+sm[S_Q+2688+e1*PT+t]
               + fb2_[e1] + sm[S_X1+e1*ST+t];
      float s  = warp_sum(v0+v1);
      float s2 = warp_sum(v0*v0+v1*v1);
      float mean = s*(1.f/64.f);
      float var  = s2*(1.f/64.f) - mean*mean;
      float r = rsqrtf(var + 1e-5f);
      sm[S_X1+e0*ST+t] = (v0-mean)*r*ln2g_[e0] + ln2b_[e0];
      sm[S_X1+e1*ST+t] = (v1-mean)*r*ln2g_[e1] + ln2b_[e1];
    }
    __syncthreads();

    // ---- LN3 merged with residual (QQ - temb) ----
    for (int t = warp; t < 12; t += 8){
      int e0 = lane, e1 = lane+32;
      float te0 = __ldg(temb + t*64+e0), te1 = __ldg(temb + t*64+e1);
      float v0 = sm[S_X1+e0*ST+t] + sm[S_QQ+e0*ST+t] - te0;
      float v1 = sm[S_X1+e1*ST+t] + sm[S_QQ+e1*ST+t] - te1;
      float s  = warp_sum(v0+v1);
      float s2 = warp_sum(v0*v0+v1*v1);
      float mean = s*(1.f/64.f);
      float var  = s2*(1.f/64.f) - mean*mean;
      float r = rsqrtf(var + 1e-5f);
      float o0 = (v0-mean)*r*lng_[e0] + lnb_[e0];
      float o1 = (v1-mean)*r*lng_[e1] + lnb_[e1];
      if (l+1 < LL){
        sm[S_QQ+e0*ST+t] = o0 + te0;
        sm[S_QQ+e1*ST+t] = o1 + te1;
      } else {
        sm[S_K+e0*ST+t] = o0;
        sm[S_K+e1*ST+t] = o1;
      }
    }
    __syncthreads();
  }

  // ---- head: conv2 over t (relu) + conv3 over e. out in S_K ----
  if (tid < 192){
    int o = tid>>4, es = (tid&15)*4;
    float w2row[12];
    #pragma unroll
    for (int t=0;t<12;t++) w2row[t] = __ldg(w2c + o*12 + t);
    float b2v = __ldg(b2c + o);
    float acc = 0.f;
    #pragma unroll
    for (int q=0;q<4;q++){
      int e = es + q;
      const float* rowp = sm + S_K + e*ST;
      float v = b2v;
      #pragma unroll
      for (int t=0;t<12;t++) v += rowp[t]*w2row[t];
      v = fmaxf(v, 0.f);
      acc += v * __ldg(w3c + e);
    }
    #pragma unroll
    for (int off=8; off; off>>=1) acc += __shfl_xor_sync(0xffffffffu, acc, off);
    if ((tid&15)==0) outp[(long)blockIdx.x*12 + o] = acc + __ldg(b3c);
  }
}

// ---------------------------------------------------------------------------
extern "C" void kernel_launch(void* const* d_in, const int* in_sizes, int n_in,
                              void* d_out, int out_size) {
  const float* x       = (const float*)d_in[0];
  const int*   adj     = (const int*)  d_in[1];
  const float* gat_W2  = (const float*)d_in[2];
  const float* gat_a   = (const float*)d_in[3];
  const float* gat_b   = (const float*)d_in[4];
  const float* conv1_w = (const float*)d_in[5];
  const float* conv1_b = (const float*)d_in[6];
  const float* temb    = (const float*)d_in[7];
  const float* Wq      = (const float*)d_in[8];
  const float* Wk      = (const float*)d_in[9];
  const float* Wv      = (const float*)d_in[10];
  const float* Wo      = (const float*)d_in[11];
  const float* bo      = (const float*)d_in[12];
  const float* ln1_g   = (const float*)d_in[13];
  const float* ln1_b   = (const float*)d_in[14];
  const float* ln2_g   = (const float*)d_in[15];
  const float* ln2_b   = (const float*)d_in[16];
  const float* ff_w1   = (const float*)d_in[17];
  const float* ff_b1   = (const float*)d_in[18];
  const float* ff_w2   = (const float*)d_in[19];
  const float* ff_b2   = (const float*)d_in[20];
  const float* lng     = (const float*)d_in[21];
  const float* lnb     = (const float*)d_in[22];
  const float* conv2_w = (const float*)d_in[23];
  const float* conv2_b = (const float*)d_in[24];
  const float* conv3_w = (const float*)d_in[25];
  const float* conv3_b = (const float*)d_in[26];
  float* outp = (float*)d_out;

  dim3 g1(BB, (NV + 1) / 2);
  k_gat<<<g1, 128>>>(x, adj, gat_W2, gat_a, gat_b, conv1_w, conv1_b);

  k_fused<<<BB*NV, 256>>>(temb, Wq, Wk, Wv, Wo, bo,
                          ln1_g, ln1_b, ln2_g, ln2_b,
                          ff_w1, ff_b1, ff_w2, ff_b2,
                          lng, lnb,
                          conv2_w, conv2_b, conv3_w, conv3_b, outp);
}